// round 8
// baseline (speedup 1.0000x reference)
#include <cuda_runtime.h>
#include <cuda_bf16.h>
#include <math.h>
#include <stdint.h>

#define S_DIM 1024
#define T_DIM 1024
#define HID_DIM 128
#define NE_MAX 32000
#define NETILES 250          // ceil(NE_MAX/128)
#define NBUCKET 33
#define BWID 32              // bucket width in tap columns
#define BCAP 2048
#define RMAX 72
#define NSTILE 8
#define EGRP 18
#define STW 128              // stageA sensor tile width
#define BTILE 34816u         // one [128][136] bf16 tile in bytes
#define LDT 136              // padded row length (bf16 elems)

// ---------------- scratch (__device__ globals) ----------------
__device__ __align__(16) __nv_bfloat16 g_respb[(size_t)NE_MAX * S_DIM];     // [e][s]
__device__ __align__(16) float g_D[(size_t)NBUCKET * BWID * S_DIM];         // [c][s]
__device__ int   g_bcnt[NBUCKET];
__device__ int   g_bidx[NBUCKET * BCAP];
__device__ float g_bz[NBUCKET * BCAP];
// bf16 weight tiles [stile][p_hi,p_lo,a_hi,a_lo][128k][136n]
__device__ __align__(16) unsigned char g_Bprep[(size_t)NSTILE * 4 * BTILE];
// precomputed hidden activations, tile layout [etile][p,a][128el][LDT k]
__device__ __align__(16) unsigned char g_Hprep[(size_t)NETILES * 2 * BTILE];

// ---------------- helpers ----------------
__device__ __forceinline__ uint32_t smem_u32(const void* p) {
    uint32_t a;
    asm("{ .reg .u64 t; cvta.to.shared.u64 t, %1; cvt.u32.u64 %0, t; }"
        : "=r"(a) : "l"(p));
    return a;
}
__device__ __forceinline__ void ldsm_x4(uint32_t* r, uint32_t addr) {
    asm volatile("ldmatrix.sync.aligned.m8n8.x4.shared.b16 {%0,%1,%2,%3}, [%4];"
                 : "=r"(r[0]), "=r"(r[1]), "=r"(r[2]), "=r"(r[3]) : "r"(addr));
}
__device__ __forceinline__ void ldsm_x4_t(uint32_t* r, uint32_t addr) {
    asm volatile("ldmatrix.sync.aligned.m8n8.x4.trans.shared.b16 {%0,%1,%2,%3}, [%4];"
                 : "=r"(r[0]), "=r"(r[1]), "=r"(r[2]), "=r"(r[3]) : "r"(addr));
}
__device__ __forceinline__ void mma_bf16(float* c, const uint32_t* a, const uint32_t* b) {
    asm volatile("mma.sync.aligned.m16n8k16.row.col.f32.bf16.bf16.f32 "
                 "{%0,%1,%2,%3}, {%4,%5,%6,%7}, {%8,%9}, {%0,%1,%2,%3};"
                 : "+f"(c[0]), "+f"(c[1]), "+f"(c[2]), "+f"(c[3])
                 : "r"(a[0]), "r"(a[1]), "r"(a[2]), "r"(a[3]), "r"(b[0]), "r"(b[1]));
}

// ---------------------------------------------------------------------------
// Prep: split W2 into bf16 hi/lo tiles [k][136] row-major.
// ---------------------------------------------------------------------------
__global__ void prep_kernel(const float* __restrict__ Wp2, const float* __restrict__ Wa2)
{
    const int stile = blockIdx.x, which = blockIdx.y;
    const int s0 = stile * 128;
    const float* W2 = (which >= 2) ? Wa2 : Wp2;
    const int split = which & 1;
    __nv_bfloat16* dst = (__nv_bfloat16*)(g_Bprep + ((size_t)stile * 4 + which) * BTILE);
    for (int idx = threadIdx.x; idx < 128 * 128; idx += 256) {
        int k = idx >> 7, n = idx & 127;
        float w = W2[(size_t)k * S_DIM + s0 + n];
        __nv_bfloat16 hi = __float2bfloat16(w);
        __nv_bfloat16 v = split ? __float2bfloat16(w - __bfloat162float(hi)) : hi;
        dst[k * LDT + n] = v;
    }
}

// ---------------------------------------------------------------------------
// PrepH: hidden layer H = relu(x@W1+b1) as bf16 A-tiles [el][k], stride LDT.
// grid (NETILES, 2).
// ---------------------------------------------------------------------------
__global__ void prepH_kernel(const float* __restrict__ x,
                             const float* __restrict__ Wp1, const float* __restrict__ bp1,
                             const float* __restrict__ Wa1, const float* __restrict__ ba1,
                             int ne)
{
    const int tile = blockIdx.x, m = blockIdx.y;
    const int tid = threadIdx.x;
    const int e0 = tile * 128;

    __shared__ __align__(16) float xs[128][3];
    __shared__ __align__(16) float W1s[3][HID_DIM];
    __shared__ __align__(16) float b1s[HID_DIM];

    const float* W1 = m ? Wa1 : Wp1;
    const float* b1 = m ? ba1 : bp1;
    for (int i = tid; i < 3 * HID_DIM; i += 256) (&W1s[0][0])[i] = W1[i];
    if (tid < HID_DIM) b1s[tid] = b1[tid];
    if (tid < 128) {
        int e = e0 + tid;
        if (e < ne) {
            xs[tid][0] = x[e * 3 + 0];
            xs[tid][1] = x[e * 3 + 1];
            xs[tid][2] = x[e * 3 + 2];
        } else {
            xs[tid][0] = 0.f; xs[tid][1] = 0.f; xs[tid][2] = 0.f;
        }
    }
    __syncthreads();

    unsigned char* dst = g_Hprep + ((size_t)tile * 2 + m) * BTILE;
    for (int i = tid; i < 8192; i += 256) {
        int el = i >> 6, k = (i & 63) * 2;
        float x0 = xs[el][0], x1 = xs[el][1], x2 = xs[el][2];
        float h0 = b1s[k]     + x0 * W1s[0][k]     + x1 * W1s[1][k]     + x2 * W1s[2][k];
        float h1 = b1s[k + 1] + x0 * W1s[0][k + 1] + x1 * W1s[1][k + 1] + x2 * W1s[2][k + 1];
        h0 = fmaxf(h0, 0.f); h1 = fmaxf(h1, 0.f);
        __nv_bfloat162 v = __floats2bfloat162_rn(h0, h1);
        *(uint32_t*)(dst + el * (LDT * 2) + k * 2) = *(uint32_t*)&v;
    }
}

// ---------------------------------------------------------------------------
// Bucket electrons (deterministic, index order), 4 per thread per round.
// Bucket b holds electrons with k=floor(z) in [32b-5, 32b+31].
// ---------------------------------------------------------------------------
__global__ void bucket_kernel(const float* __restrict__ zpos, int ne)
{
    const int b = blockIdx.x;
    const int tid = threadIdx.x;
    const float lob = (float)(b * BWID - 5);
    const float hib = (float)(b * BWID + BWID);

    __shared__ int wsum[4][8];
    __shared__ int base0;
    if (tid == 0) base0 = 0;
    __syncthreads();

    const int lane = tid & 31, w = tid >> 5;
    for (int cb = 0; cb < ne; cb += 1024) {
        float z[4]; bool kp[4]; unsigned bm[4];
#pragma unroll
        for (int q = 0; q < 4; q++) {
            int e = cb + q * 256 + tid;
            kp[q] = false; z[q] = 0.f;
            if (e < ne) { z[q] = zpos[e]; kp[q] = (z[q] >= lob) && (z[q] < hib); }
        }
#pragma unroll
        for (int q = 0; q < 4; q++) bm[q] = __ballot_sync(0xffffffffu, kp[q]);
        if (lane == 0)
#pragma unroll
            for (int q = 0; q < 4; q++) wsum[q][w] = __popc(bm[q]);
        __syncthreads();
        if (tid == 0) {
            int run = base0;
#pragma unroll
            for (int q = 0; q < 4; q++)
#pragma unroll
                for (int ww = 0; ww < 8; ww++) {
                    int t = wsum[q][ww]; wsum[q][ww] = run; run += t;
                }
            base0 = run;
        }
        __syncthreads();
#pragma unroll
        for (int q = 0; q < 4; q++) {
            if (kp[q]) {
                int p = wsum[q][w] + __popc(bm[q] & ((1u << lane) - 1u));
                if (p < BCAP) {
                    g_bidx[b * BCAP + p] = cb + q * 256 + tid;
                    g_bz[b * BCAP + p] = z[q];
                }
            }
        }
        __syncthreads();
    }
    if (tid == 0) g_bcnt[b] = (base0 < BCAP) ? base0 : BCAP;
}

// ---------------------------------------------------------------------------
// MLP via mma.sync bf16. Grid (NSTILE=8, EGRP=18), 256 threads / 8 warps.
// A tiles (H) precomputed; CTA copies them from gmem. B (4 tiles) resident.
// ---------------------------------------------------------------------------
__global__ __launch_bounds__(256, 1)
void mlp_mma_kernel(const float* __restrict__ maskv,
                    const float* __restrict__ bp2, const float* __restrict__ ba2,
                    int ne)
{
    extern __shared__ __align__(16) unsigned char dyn[];
    __shared__ __align__(16) float bb[2][128];

    const int tid = threadIdx.x;
    const int wid = tid >> 5, lane = tid & 31;
    const int wy = wid >> 1;          // 0..3 over electrons
    const int wx = wid & 1;           // 0..1 over sensors
    const int stile = blockIdx.x, gy = blockIdx.y;
    const int s0 = stile * 128;
    const int ntiles = (ne + 127) / 128;

    unsigned char* Ap = dyn;                 // [128][LDT] bf16, prob
    unsigned char* Aa = dyn + BTILE;         // amp
    unsigned char* Bt = dyn + 2 * BTILE;     // 4 weight tiles

    for (int i = tid; i < 128; i += 256) {
        bb[0][i] = bp2[s0 + i];
        bb[1][i] = ba2[s0 + i];
    }
    {
        const uint4* src = (const uint4*)(g_Bprep + (size_t)stile * 4 * BTILE);
        uint4* d4 = (uint4*)Bt;
        for (int i = tid; i < (int)(4 * BTILE / 16); i += 256) d4[i] = src[i];
    }
    __syncthreads();

    const uint32_t ApS = smem_u32(Ap), AaS = smem_u32(Aa), BtS = smem_u32(Bt);
    const uint32_t lmOff = (uint32_t)(lane & 15) * (LDT * 2) + (uint32_t)(lane >> 4) * 16;

    for (int et = gy; et < ntiles; et += EGRP) {
        const int e0 = et * 128;

        __syncthreads();   // all warps done reading previous A tiles
        {
            const uint4* asrc = (const uint4*)(g_Hprep + (size_t)et * 2 * BTILE);
            uint4* ad = (uint4*)Ap;          // Ap,Aa contiguous
#pragma unroll
            for (int r = 0; r < 17; r++) {
                int i = r * 256 + tid;       // 2*BTILE/16 = 4352 = 17*256
                ad[i] = asrc[i];
            }
        }
        __syncthreads();

        float accP[2][8][4], accA[2][8][4];
#pragma unroll
        for (int mt = 0; mt < 2; mt++)
#pragma unroll
            for (int nt = 0; nt < 8; nt++)
#pragma unroll
                for (int j = 0; j < 4; j++) { accP[mt][nt][j] = 0.f; accA[mt][nt][j] = 0.f; }

#pragma unroll
        for (int sp = 0; sp < 2; sp++) {
            const uint32_t BpS = BtS + (uint32_t)sp * BTILE;
            const uint32_t BaS = BtS + (uint32_t)(2 + sp) * BTILE;
#pragma unroll
            for (int ks = 0; ks < 8; ks++) {
                const uint32_t kb = (uint32_t)ks * 32;
                const uint32_t krow = (uint32_t)ks * 16 * (LDT * 2);
                uint32_t a0[4], a1[4], bf[4][4];
                // ---- prob MLP ----
                ldsm_x4(a0, ApS + (uint32_t)(wy * 32) * (LDT * 2) + kb + lmOff);
                ldsm_x4(a1, ApS + (uint32_t)(wy * 32 + 16) * (LDT * 2) + kb + lmOff);
#pragma unroll
                for (int nb = 0; nb < 4; nb++)
                    ldsm_x4_t(bf[nb], BpS + krow + (uint32_t)(wx * 64 + nb * 16) * 2 + lmOff);
#pragma unroll
                for (int nb = 0; nb < 4; nb++) {
                    mma_bf16(accP[0][2 * nb],     a0, &bf[nb][0]);
                    mma_bf16(accP[0][2 * nb + 1], a0, &bf[nb][2]);
                    mma_bf16(accP[1][2 * nb],     a1, &bf[nb][0]);
                    mma_bf16(accP[1][2 * nb + 1], a1, &bf[nb][2]);
                }
                // ---- amp MLP ----
                ldsm_x4(a0, AaS + (uint32_t)(wy * 32) * (LDT * 2) + kb + lmOff);
                ldsm_x4(a1, AaS + (uint32_t)(wy * 32 + 16) * (LDT * 2) + kb + lmOff);
#pragma unroll
                for (int nb = 0; nb < 4; nb++)
                    ldsm_x4_t(bf[nb], BaS + krow + (uint32_t)(wx * 64 + nb * 16) * 2 + lmOff);
#pragma unroll
                for (int nb = 0; nb < 4; nb++) {
                    mma_bf16(accA[0][2 * nb],     a0, &bf[nb][0]);
                    mma_bf16(accA[0][2 * nb + 1], a0, &bf[nb][2]);
                    mma_bf16(accA[1][2 * nb],     a1, &bf[nb][0]);
                    mma_bf16(accA[1][2 * nb + 1], a1, &bf[nb][2]);
                }
            }
        }

        // epilogue: fused bias+sigmoid+amp+mask, bf16 stores
        const int rbase = wy * 32 + (lane >> 2);
        const int colb = wx * 64 + (lane & 3) * 2;
#pragma unroll
        for (int mt = 0; mt < 2; mt++) {
            int ra = e0 + rbase + mt * 16;
            int rb = ra + 8;
            float mka = (ra < ne) ? maskv[ra] : 0.f;
            float mkb = (rb < ne) ? maskv[rb] : 0.f;
#pragma unroll
            for (int nt = 0; nt < 8; nt++) {
                int col = colb + nt * 8;
                float bp0 = bb[0][col], bp1v = bb[0][col + 1];
                float ba0 = bb[1][col], ba1v = bb[1][col + 1];
                float p0 = accP[mt][nt][0] + bp0, p1 = accP[mt][nt][1] + bp1v;
                float p2 = accP[mt][nt][2] + bp0, p3 = accP[mt][nt][3] + bp1v;
                float A0 = accA[mt][nt][0] + ba0, A1 = accA[mt][nt][1] + ba1v;
                float A2 = accA[mt][nt][2] + ba0, A3 = accA[mt][nt][3] + ba1v;
                float o0 = A0 * mka * (1.0f / (1.0f + expf(-p0)));
                float o1 = A1 * mka * (1.0f / (1.0f + expf(-p1)));
                float o2 = A2 * mkb * (1.0f / (1.0f + expf(-p2)));
                float o3 = A3 * mkb * (1.0f / (1.0f + expf(-p3)));
                if (ra < ne) *(__nv_bfloat162*)&g_respb[(size_t)ra * S_DIM + s0 + col] =
                    __floats2bfloat162_rn(o0, o1);
                if (rb < ne) *(__nv_bfloat162*)&g_respb[(size_t)rb * S_DIM + s0 + col] =
                    __floats2bfloat162_rn(o2, o3);
            }
        }
    }
}

// ---------------------------------------------------------------------------
// Stage A: register-gather tap accumulation. grid (8 s-tiles x 33 buckets),
// 256 threads. Warp w owns tap columns [4w, 4w+4); lane covers 4 sensors
// (lane, +32, +64, +96). All accumulation in registers; no slab RMW.
// Deterministic: electron index order per thread.
// ---------------------------------------------------------------------------
__global__ __launch_bounds__(256)
void stageA_kernel()
{
    const int s0 = blockIdx.x * STW;
    const int b = blockIdx.y;
    const int tid = threadIdx.x;
    const int warp = tid >> 5, lane = tid & 31;
    const int clb = warp * 4;

    __shared__ __align__(16) float rs[128][STW];   // 64 KB staged resp (fp32)
    __shared__ float wc[128][6];
    __shared__ int   kc[128];
    __shared__ int   ech[128];

    float acc[4][4];
#pragma unroll
    for (int q = 0; q < 4; q++)
#pragma unroll
        for (int h = 0; h < 4; h++) acc[q][h] = 0.f;

    const int cnt = g_bcnt[b];
    const int c0 = b * BWID;

    for (int base = 0; base < cnt; base += 128) {
        int n = cnt - base; if (n > 128) n = 128;
        if (tid < n) {
            float z = g_bz[b * BCAP + base + tid];
            float kf = floorf(z);
            float f = z - kf;
            float t0 = f + 2.f, t1 = f + 1.f, t2 = f, t3 = f - 1.f,
                  t4 = f - 2.f, t5 = f - 3.f;
            wc[tid][0] = t1 * t2 * t3 * t4 * t5 * (-1.f / 120.f);
            wc[tid][1] = t0 * t2 * t3 * t4 * t5 * ( 1.f /  24.f);
            wc[tid][2] = t0 * t1 * t3 * t4 * t5 * (-1.f /  12.f);
            wc[tid][3] = t0 * t1 * t2 * t4 * t5 * ( 1.f /  12.f);
            wc[tid][4] = t0 * t1 * t2 * t3 * t5 * (-1.f /  24.f);
            wc[tid][5] = t0 * t1 * t2 * t3 * t4 * ( 1.f / 120.f);
            kc[tid] = (int)kf - c0;
            ech[tid] = g_bidx[b * BCAP + base + tid];
        }
        __syncthreads();

        // stage resp chunk: n rows x STW sensors, bf16 -> fp32
        for (int i = tid; i < n * (STW / 2); i += 256) {
            int e = i / (STW / 2);
            int c = i - e * (STW / 2);
            __nv_bfloat162 bv =
                *(const __nv_bfloat162*)&g_respb[(size_t)ech[e] * S_DIM + s0 + c * 2];
            float2 fv = __bfloat1622float2(bv);
            *(float2*)&rs[e][c * 2] = fv;
        }
        __syncthreads();

        for (int i = 0; i < n; i++) {
            int cl0 = kc[i];                       // in [-5, 31]
            if (clb + 3 >= cl0 && clb <= cl0 + 5) {
                float w[4];
#pragma unroll
                for (int q = 0; q < 4; q++) {
                    int j = clb + q - cl0;
                    w[q] = (j >= 0 && j < 6) ? wc[i][j] : 0.f;
                }
#pragma unroll
                for (int h = 0; h < 4; h++) {
                    float r = rs[i][lane + 32 * h];
#pragma unroll
                    for (int q = 0; q < 4; q++)
                        acc[q][h] = fmaf(r, w[q], acc[q][h]);
                }
            }
        }
        __syncthreads();
    }

#pragma unroll
    for (int q = 0; q < 4; q++)
#pragma unroll
        for (int h = 0; h < 4; h++)
            g_D[(size_t)(c0 + clb + q) * S_DIM + s0 + 32 * h + lane] = acc[q][h];
}

// ---------------------------------------------------------------------------
// Banded 1-D convolution out[s,t] = sum_tau D[tau+2,s] * G(t-tau).
// ---------------------------------------------------------------------------
__global__ __launch_bounds__(256)
void conv_kernel(const float* __restrict__ sig, float* __restrict__ out)
{
    __shared__ float Db[2 * RMAX + 33][64];
    __shared__ float Gs[2 * RMAX + 1];

    const int s0 = blockIdx.x * 64;
    const int t0 = blockIdx.y * 32;
    const int tid = threadIdx.x;

    const float sigma  = sig[0];
    const float inv2s2 = 1.0f / (2.0f * sigma * sigma);
    const float coef   = 0.3989422804f / sqrtf(sigma * sigma);
    int R = (int)ceilf(sigma * 7.746f);
    if (R < 1) R = 1;
    if (R > RMAX) R = RMAX;
    const int nG = 2 * R + 1;
    const int rows = 2 * R + 33;
    const int rlo = t0 - R + 2;

    for (int i = tid; i < nG; i += 256) {
        float d = (float)(i - R);
        Gs[i] = coef * expf(-d * d * inv2s2);
    }
    for (int idx = tid; idx < rows * 64; idx += 256) {
        int ri = idx >> 6, s2 = idx & 63;
        int c = rlo + ri;
        Db[ri][s2] = (c >= 0 && c < T_DIM + 4) ?
            g_D[(size_t)c * S_DIM + s0 + s2] : 0.f;
    }
    __syncthreads();

    const int sl = tid & 31;
    const int tq = tid >> 5;
    const int tb = tq * 4;

    float acc0[4] = {0.f, 0.f, 0.f, 0.f};
    float acc1[4] = {0.f, 0.f, 0.f, 0.f};

    for (int ri = 0; ri < rows; ri++) {
        float v0 = Db[ri][sl];
        float v1 = Db[ri][sl + 32];
#pragma unroll
        for (int k = 0; k < 4; k++) {
            int gi = ri - tb - k;
            if (gi >= 0 && gi < nG) {
                float w = Gs[gi];
                acc0[k] = fmaf(v0, w, acc0[k]);
                acc1[k] = fmaf(v1, w, acc1[k]);
            }
        }
    }

    *(float4*)&out[(size_t)(s0 + sl) * T_DIM + t0 + tb] =
        make_float4(acc0[0], acc0[1], acc0[2], acc0[3]);
    *(float4*)&out[(size_t)(s0 + sl + 32) * T_DIM + t0 + tb] =
        make_float4(acc1[0], acc1[1], acc1[2], acc1[3]);
}

// ---------------------------------------------------------------------------
extern "C" void kernel_launch(void* const* d_in, const int* in_sizes, int n_in,
                              void* d_out, int out_size)
{
    const float* x    = (const float*)d_in[0];
    const float* zpos = (const float*)d_in[1];
    const float* mask = (const float*)d_in[2];
    const float* Wp1  = (const float*)d_in[3];
    const float* bp1  = (const float*)d_in[4];
    const float* Wp2  = (const float*)d_in[5];
    const float* bp2  = (const float*)d_in[6];
    const float* Wa1  = (const float*)d_in[7];
    const float* ba1  = (const float*)d_in[8];
    const float* Wa2  = (const float*)d_in[9];
    const float* ba2  = (const float*)d_in[10];
    const float* sig  = (const float*)d_in[11];

    int ne = in_sizes[1];
    if (ne > NE_MAX) ne = NE_MAX;
    int ntiles = (ne + 127) / 128;

    const int dyn_bytes = 6 * BTILE;   // 2 A tiles + 4 B tiles = 208896 B
    cudaFuncSetAttribute(mlp_mma_kernel,
                         cudaFuncAttributeMaxDynamicSharedMemorySize, dyn_bytes);

    prep_kernel<<<dim3(NSTILE, 4), 256>>>(Wp2, Wa2);
    prepH_kernel<<<dim3(ntiles, 2), 256>>>(x, Wp1, bp1, Wa1, ba1, ne);
    bucket_kernel<<<NBUCKET, 256>>>(zpos, ne);

    mlp_mma_kernel<<<dim3(NSTILE, EGRP), 256, dyn_bytes>>>(mask, bp2, ba2, ne);

    stageA_kernel<<<dim3(S_DIM / STW, NBUCKET), 256>>>();

    conv_kernel<<<dim3(S_DIM / 64, T_DIM / 32), 256>>>(sig, (float*)d_out);
}

// round 9
// speedup vs baseline: 1.4841x; 1.4841x over previous
#include <cuda_runtime.h>
#include <cuda_bf16.h>
#include <math.h>
#include <stdint.h>

#define S_DIM 1024
#define T_DIM 1024
#define HID_DIM 128
#define NE_MAX 32000
#define NETILES 250          // ceil(NE_MAX/128)
#define NBUCKET 33
#define BWID 32              // bucket width in tap columns
#define BCAP 2048
#define RMAX 72
#define NSTILE 8
#define EGRP 18
#define BTILE 34816u         // one [128][136] bf16 tile in bytes
#define LDT 136              // padded row length (bf16 elems)
#define LDB (LDT * 2)        // row bytes = 272

// ---------------- scratch (__device__ globals) ----------------
__device__ __align__(16) __nv_bfloat16 g_respb[(size_t)NE_MAX * S_DIM];     // [e][s]
__device__ __align__(16) float g_D[(size_t)NBUCKET * BWID * S_DIM];         // [c][s]
__device__ int   g_bcnt[NBUCKET];
__device__ int   g_bidx[NBUCKET * BCAP];
__device__ float g_bz[NBUCKET * BCAP];
// bf16 weight tiles [stile][p_hi,p_lo,a_hi,a_lo][128k][136n]
__device__ __align__(16) unsigned char g_Bprep[(size_t)NSTILE * 4 * BTILE];
// precomputed hidden activations [etile][p,a][128el][LDT k]
__device__ __align__(16) unsigned char g_Hprep[(size_t)NETILES * 2 * BTILE];

// ---------------- helpers ----------------
__device__ __forceinline__ uint32_t smem_u32(const void* p) {
    uint32_t a;
    asm("{ .reg .u64 t; cvta.to.shared.u64 t, %1; cvt.u32.u64 %0, t; }"
        : "=r"(a) : "l"(p));
    return a;
}
__device__ __forceinline__ void ldsm_x4(uint32_t* r, uint32_t addr) {
    asm volatile("ldmatrix.sync.aligned.m8n8.x4.shared.b16 {%0,%1,%2,%3}, [%4];"
                 : "=r"(r[0]), "=r"(r[1]), "=r"(r[2]), "=r"(r[3]) : "r"(addr));
}
__device__ __forceinline__ void ldsm_x4_t(uint32_t* r, uint32_t addr) {
    asm volatile("ldmatrix.sync.aligned.m8n8.x4.trans.shared.b16 {%0,%1,%2,%3}, [%4];"
                 : "=r"(r[0]), "=r"(r[1]), "=r"(r[2]), "=r"(r[3]) : "r"(addr));
}
__device__ __forceinline__ void mma_bf16(float* c, const uint32_t* a, const uint32_t* b) {
    asm volatile("mma.sync.aligned.m16n8k16.row.col.f32.bf16.bf16.f32 "
                 "{%0,%1,%2,%3}, {%4,%5,%6,%7}, {%8,%9}, {%0,%1,%2,%3};"
                 : "+f"(c[0]), "+f"(c[1]), "+f"(c[2]), "+f"(c[3])
                 : "r"(a[0]), "r"(a[1]), "r"(a[2]), "r"(a[3]), "r"(b[0]), "r"(b[1]));
}

// ---------------------------------------------------------------------------
// Prep: split W2 into bf16 hi/lo tiles [k][136] row-major.
// ---------------------------------------------------------------------------
__global__ void prep_kernel(const float* __restrict__ Wp2, const float* __restrict__ Wa2)
{
    const int stile = blockIdx.x, which = blockIdx.y;
    const int s0 = stile * 128;
    const float* W2 = (which >= 2) ? Wa2 : Wp2;
    const int split = which & 1;
    __nv_bfloat16* dst = (__nv_bfloat16*)(g_Bprep + ((size_t)stile * 4 + which) * BTILE);
    for (int idx = threadIdx.x; idx < 128 * 128; idx += 256) {
        int k = idx >> 7, n = idx & 127;
        float w = W2[(size_t)k * S_DIM + s0 + n];
        __nv_bfloat16 hi = __float2bfloat16(w);
        __nv_bfloat16 v = split ? __float2bfloat16(w - __bfloat162float(hi)) : hi;
        dst[k * LDT + n] = v;
    }
}

// ---------------------------------------------------------------------------
// PrepH: hidden layer H = relu(x@W1+b1) as bf16 A-tiles [el][k], stride LDT.
// ---------------------------------------------------------------------------
__global__ void prepH_kernel(const float* __restrict__ x,
                             const float* __restrict__ Wp1, const float* __restrict__ bp1,
                             const float* __restrict__ Wa1, const float* __restrict__ ba1,
                             int ne)
{
    const int tile = blockIdx.x, m = blockIdx.y;
    const int tid = threadIdx.x;
    const int e0 = tile * 128;

    __shared__ __align__(16) float xs[128][3];
    __shared__ __align__(16) float W1s[3][HID_DIM];
    __shared__ __align__(16) float b1s[HID_DIM];

    const float* W1 = m ? Wa1 : Wp1;
    const float* b1 = m ? ba1 : bp1;
    for (int i = tid; i < 3 * HID_DIM; i += 256) (&W1s[0][0])[i] = W1[i];
    if (tid < HID_DIM) b1s[tid] = b1[tid];
    if (tid < 128) {
        int e = e0 + tid;
        if (e < ne) {
            xs[tid][0] = x[e * 3 + 0];
            xs[tid][1] = x[e * 3 + 1];
            xs[tid][2] = x[e * 3 + 2];
        } else {
            xs[tid][0] = 0.f; xs[tid][1] = 0.f; xs[tid][2] = 0.f;
        }
    }
    __syncthreads();

    unsigned char* dst = g_Hprep + ((size_t)tile * 2 + m) * BTILE;
    for (int i = tid; i < 8192; i += 256) {
        int el = i >> 6, k = (i & 63) * 2;
        float x0 = xs[el][0], x1 = xs[el][1], x2 = xs[el][2];
        float h0 = b1s[k]     + x0 * W1s[0][k]     + x1 * W1s[1][k]     + x2 * W1s[2][k];
        float h1 = b1s[k + 1] + x0 * W1s[0][k + 1] + x1 * W1s[1][k + 1] + x2 * W1s[2][k + 1];
        h0 = fmaxf(h0, 0.f); h1 = fmaxf(h1, 0.f);
        __nv_bfloat162 v = __floats2bfloat162_rn(h0, h1);
        *(uint32_t*)(dst + el * LDB + k * 2) = *(uint32_t*)&v;
    }
}

// ---------------------------------------------------------------------------
// Bucket electrons (deterministic, index order), 4 per thread per round.
// Bucket b holds electrons with k=floor(z) in [32b-5, 32b+31].
// ---------------------------------------------------------------------------
__global__ void bucket_kernel(const float* __restrict__ zpos, int ne)
{
    const int b = blockIdx.x;
    const int tid = threadIdx.x;
    const float lob = (float)(b * BWID - 5);
    const float hib = (float)(b * BWID + BWID);

    __shared__ int wsum[4][8];
    __shared__ int base0;
    if (tid == 0) base0 = 0;
    __syncthreads();

    const int lane = tid & 31, w = tid >> 5;
    for (int cb = 0; cb < ne; cb += 1024) {
        float z[4]; bool kp[4]; unsigned bm[4];
#pragma unroll
        for (int q = 0; q < 4; q++) {
            int e = cb + q * 256 + tid;
            kp[q] = false; z[q] = 0.f;
            if (e < ne) { z[q] = zpos[e]; kp[q] = (z[q] >= lob) && (z[q] < hib); }
        }
#pragma unroll
        for (int q = 0; q < 4; q++) bm[q] = __ballot_sync(0xffffffffu, kp[q]);
        if (lane == 0)
#pragma unroll
            for (int q = 0; q < 4; q++) wsum[q][w] = __popc(bm[q]);
        __syncthreads();
        if (tid == 0) {
            int run = base0;
#pragma unroll
            for (int q = 0; q < 4; q++)
#pragma unroll
                for (int ww = 0; ww < 8; ww++) {
                    int t = wsum[q][ww]; wsum[q][ww] = run; run += t;
                }
            base0 = run;
        }
        __syncthreads();
#pragma unroll
        for (int q = 0; q < 4; q++) {
            if (kp[q]) {
                int p = wsum[q][w] + __popc(bm[q] & ((1u << lane) - 1u));
                if (p < BCAP) {
                    g_bidx[b * BCAP + p] = cb + q * 256 + tid;
                    g_bz[b * BCAP + p] = z[q];
                }
            }
        }
        __syncthreads();
    }
    if (tid == 0) g_bcnt[b] = (base0 < BCAP) ? base0 : BCAP;
}

// ---------------------------------------------------------------------------
// MLP via mma.sync bf16. Grid (NSTILE=8, EGRP=18), 512 threads / 16 warps.
// Warp tile 16e x 64s (warps: 8 over e, 2 over s). B (4 tiles) resident.
// ---------------------------------------------------------------------------
__global__ __launch_bounds__(512, 1)
void mlp_mma_kernel(const float* __restrict__ maskv,
                    const float* __restrict__ bp2, const float* __restrict__ ba2,
                    int ne)
{
    extern __shared__ __align__(16) unsigned char dyn[];
    __shared__ __align__(16) float bb[2][128];

    const int tid = threadIdx.x;
    const int wid = tid >> 5, lane = tid & 31;
    const int wy = wid >> 1;          // 0..7 over electrons (16 each)
    const int wx = wid & 1;           // 0..1 over sensors (64 each)
    const int stile = blockIdx.x, gy = blockIdx.y;
    const int s0 = stile * 128;
    const int ntiles = (ne + 127) / 128;

    unsigned char* Ap = dyn;                 // [128][LDT] bf16, prob
    unsigned char* Aa = dyn + BTILE;         // amp
    unsigned char* Bt = dyn + 2 * BTILE;     // 4 weight tiles

    if (tid < 128) {
        bb[0][tid] = bp2[s0 + tid];
        bb[1][tid] = ba2[s0 + tid];
    }
    {
        const uint4* src = (const uint4*)(g_Bprep + (size_t)stile * 4 * BTILE);
        uint4* d4 = (uint4*)Bt;
        for (int i = tid; i < (int)(4 * BTILE / 16); i += 512) d4[i] = src[i];
    }
    __syncthreads();

    const uint32_t ApS = smem_u32(Ap), AaS = smem_u32(Aa), BtS = smem_u32(Bt);
    const uint32_t lmOff = (uint32_t)(lane & 15) * LDB + (uint32_t)(lane >> 4) * 16;

    for (int et = gy; et < ntiles; et += EGRP) {
        const int e0 = et * 128;

        __syncthreads();   // all warps done reading previous A tiles
        {
            const uint4* asrc = (const uint4*)(g_Hprep + (size_t)et * 2 * BTILE);
            uint4* ad = (uint4*)Ap;          // Ap,Aa contiguous: 4352 uint4
            for (int i = tid; i < 4352; i += 512) ad[i] = asrc[i];
        }
        __syncthreads();

        float accP[8][4], accA[8][4];
#pragma unroll
        for (int nt = 0; nt < 8; nt++)
#pragma unroll
            for (int j = 0; j < 4; j++) { accP[nt][j] = 0.f; accA[nt][j] = 0.f; }

        const uint32_t aRow = (uint32_t)(wy * 16) * LDB + lmOff;
#pragma unroll
        for (int sp = 0; sp < 2; sp++) {
            const uint32_t BpS = BtS + (uint32_t)sp * BTILE;
            const uint32_t BaS = BtS + (uint32_t)(2 + sp) * BTILE;
#pragma unroll
            for (int ks = 0; ks < 8; ks++) {
                const uint32_t kb = (uint32_t)ks * 32;
                const uint32_t krow = (uint32_t)ks * 16 * LDB;
                uint32_t a0[4], bf[4][4];
                // ---- prob MLP ----
                ldsm_x4(a0, ApS + aRow + kb);
#pragma unroll
                for (int nb = 0; nb < 4; nb++)
                    ldsm_x4_t(bf[nb], BpS + krow + (uint32_t)(wx * 64 + nb * 16) * 2 + lmOff);
#pragma unroll
                for (int nb = 0; nb < 4; nb++) {
                    mma_bf16(accP[2 * nb],     a0, &bf[nb][0]);
                    mma_bf16(accP[2 * nb + 1], a0, &bf[nb][2]);
                }
                // ---- amp MLP ----
                ldsm_x4(a0, AaS + aRow + kb);
#pragma unroll
                for (int nb = 0; nb < 4; nb++)
                    ldsm_x4_t(bf[nb], BaS + krow + (uint32_t)(wx * 64 + nb * 16) * 2 + lmOff);
#pragma unroll
                for (int nb = 0; nb < 4; nb++) {
                    mma_bf16(accA[2 * nb],     a0, &bf[nb][0]);
                    mma_bf16(accA[2 * nb + 1], a0, &bf[nb][2]);
                }
            }
        }

        // epilogue: fused bias+sigmoid+amp+mask, bf16 stores
        int ra = e0 + wy * 16 + (lane >> 2);
        int rb = ra + 8;
        float mka = (ra < ne) ? maskv[ra] : 0.f;
        float mkb = (rb < ne) ? maskv[rb] : 0.f;
        const int colb = wx * 64 + (lane & 3) * 2;
#pragma unroll
        for (int nt = 0; nt < 8; nt++) {
            int col = colb + nt * 8;
            float bp0 = bb[0][col], bp1v = bb[0][col + 1];
            float ba0 = bb[1][col], ba1v = bb[1][col + 1];
            float p0 = accP[nt][0] + bp0, p1 = accP[nt][1] + bp1v;
            float p2 = accP[nt][2] + bp0, p3 = accP[nt][3] + bp1v;
            float A0 = accA[nt][0] + ba0, A1 = accA[nt][1] + ba1v;
            float A2 = accA[nt][2] + ba0, A3 = accA[nt][3] + ba1v;
            float o0 = A0 * mka * (1.0f / (1.0f + expf(-p0)));
            float o1 = A1 * mka * (1.0f / (1.0f + expf(-p1)));
            float o2 = A2 * mkb * (1.0f / (1.0f + expf(-p2)));
            float o3 = A3 * mkb * (1.0f / (1.0f + expf(-p3)));
            if (ra < ne) *(__nv_bfloat162*)&g_respb[(size_t)ra * S_DIM + s0 + col] =
                __floats2bfloat162_rn(o0, o1);
            if (rb < ne) *(__nv_bfloat162*)&g_respb[(size_t)rb * S_DIM + s0 + col] =
                __floats2bfloat162_rn(o2, o3);
        }
    }
}

// ---------------------------------------------------------------------------
// Stage A as dense GEMM per bucket: D[32, s] = W[32, e] @ resp[e, s].
// W[c,e] = lagrange6 tap weight (bf16, built in smem per 128-electron chunk).
// grid (8 s-tiles of 128, 33 buckets), 256 threads / 8 warps = 2(M16) x 4(N32).
// ---------------------------------------------------------------------------
__global__ __launch_bounds__(256)
void stageA_kernel()
{
    const int s0 = blockIdx.x * 128;
    const int b = blockIdx.y;
    const int tid = threadIdx.x;
    const int wid = tid >> 5, lane = tid & 31;
    const int wm = wid >> 2;          // 0..1 (16 tap rows each)
    const int wn = wid & 3;           // 0..3 (32 sensors each)

    __shared__ __align__(16) unsigned char Wt[32 * LDB];      // [32 c][136 e] bf16
    __shared__ __align__(16) unsigned char Rt[128 * LDB];     // [128 e][136 s] bf16
    __shared__ int ech[128];

    const int cnt = g_bcnt[b];
    const int c0 = b * BWID;

    float acc[4][4];
#pragma unroll
    for (int nt = 0; nt < 4; nt++)
#pragma unroll
        for (int j = 0; j < 4; j++) acc[nt][j] = 0.f;

    const uint32_t WtS = smem_u32(Wt), RtS = smem_u32(Rt);
    const uint32_t lmOff = (uint32_t)(lane & 15) * LDB + (uint32_t)(lane >> 4) * 16;

    for (int base = 0; base < cnt; base += 128) {
        int n = cnt - base; if (n > 128) n = 128;

        // electron meta into regs (LDG issues early)
        float z = 0.f; int eidx = 0;
        if (tid < n) {
            z = g_bz[b * BCAP + base + tid];
            eidx = g_bidx[b * BCAP + base + tid];
        }

        // zero W tile (32*LDB/4 = 2176 words)
        for (int i = tid; i < 32 * LDB / 4; i += 256) ((uint32_t*)Wt)[i] = 0u;
        if (tid < n) ech[tid] = eidx;
        __syncthreads();

        // scatter tap weights: column tid, rows kl..kl+5 clipped to [0,32)
        if (tid < n) {
            float kf = floorf(z);
            float f = z - kf;
            int kl = (int)kf - c0;                 // in [-5, 31]
            float t0 = f + 2.f, t1 = f + 1.f, t2 = f, t3 = f - 1.f,
                  t4 = f - 2.f, t5 = f - 3.f;
            float w[6];
            w[0] = t1 * t2 * t3 * t4 * t5 * (-1.f / 120.f);
            w[1] = t0 * t2 * t3 * t4 * t5 * ( 1.f /  24.f);
            w[2] = t0 * t1 * t3 * t4 * t5 * (-1.f /  12.f);
            w[3] = t0 * t1 * t2 * t4 * t5 * ( 1.f /  12.f);
            w[4] = t0 * t1 * t2 * t3 * t5 * (-1.f /  24.f);
            w[5] = t0 * t1 * t2 * t3 * t4 * ( 1.f / 120.f);
#pragma unroll
            for (int j = 0; j < 6; j++) {
                int c = kl + j;
                if (c >= 0 && c < 32)
                    *(__nv_bfloat16*)(Wt + c * LDB + tid * 2) = __float2bfloat16(w[j]);
            }
        }

        // copy resp rows (bf16): n rows x 256 B = n*16 uint4
        for (int i = tid; i < n * 16; i += 256) {
            int e = i >> 4, q = i & 15;
            ((uint4*)(Rt + e * LDB))[q] =
                ((const uint4*)&g_respb[(size_t)ech[e] * S_DIM + s0])[q];
        }
        __syncthreads();

        // mma: 8 k-steps of 16 electrons (stale rows beyond n have W cols = 0)
#pragma unroll
        for (int ks = 0; ks < 8; ks++) {
            uint32_t a0[4], bf[2][4];
            ldsm_x4(a0, WtS + (uint32_t)(wm * 16) * LDB + (uint32_t)ks * 32 + lmOff);
#pragma unroll
            for (int nb = 0; nb < 2; nb++)
                ldsm_x4_t(bf[nb], RtS + (uint32_t)(ks * 16) * LDB +
                                  (uint32_t)(wn * 32 + nb * 16) * 2 + lmOff);
#pragma unroll
            for (int nb = 0; nb < 2; nb++) {
                mma_bf16(acc[2 * nb],     a0, &bf[nb][0]);
                mma_bf16(acc[2 * nb + 1], a0, &bf[nb][2]);
            }
        }
        __syncthreads();
    }

    // store D: rows c0 + wm*16 + {lane>>2, +8}, cols s0 + wn*32 + nt*8 + (lane&3)*2
    const int r0 = c0 + wm * 16 + (lane >> 2);
    const int colb = s0 + wn * 32 + (lane & 3) * 2;
#pragma unroll
    for (int nt = 0; nt < 4; nt++) {
        int col = colb + nt * 8;
        *(float2*)&g_D[(size_t)r0 * S_DIM + col] = make_float2(acc[nt][0], acc[nt][1]);
        *(float2*)&g_D[(size_t)(r0 + 8) * S_DIM + col] = make_float2(acc[nt][2], acc[nt][3]);
    }
}

// ---------------------------------------------------------------------------
// Banded 1-D convolution out[s,t] = sum_tau D[tau+2,s] * G(t-tau).
// ---------------------------------------------------------------------------
__global__ __launch_bounds__(256)
void conv_kernel(const float* __restrict__ sig, float* __restrict__ out)
{
    __shared__ float Db[2 * RMAX + 33][64];
    __shared__ float Gs[2 * RMAX + 1];

    const int s0 = blockIdx.x * 64;
    const int t0 = blockIdx.y * 32;
    const int tid = threadIdx.x;

    const float sigma  = sig[0];
    const float inv2s2 = 1.0f / (2.0f * sigma * sigma);
    const float coef   = 0.3989422804f / sqrtf(sigma * sigma);
    int R = (int)ceilf(sigma * 7.746f);
    if (R < 1) R = 1;
    if (R > RMAX) R = RMAX;
    const int nG = 2 * R + 1;
    const int rows = 2 * R + 33;
    const int rlo = t0 - R + 2;

    for (int i = tid; i < nG; i += 256) {
        float d = (float)(i - R);
        Gs[i] = coef * expf(-d * d * inv2s2);
    }
    for (int idx = tid; idx < rows * 64; idx += 256) {
        int ri = idx >> 6, s2 = idx & 63;
        int c = rlo + ri;
        Db[ri][s2] = (c >= 0 && c < T_DIM + 4) ?
            g_D[(size_t)c * S_DIM + s0 + s2] : 0.f;
    }
    __syncthreads();

    const int sl = tid & 31;
    const int tq = tid >> 5;
    const int tb = tq * 4;

    float acc0[4] = {0.f, 0.f, 0.f, 0.f};
    float acc1[4] = {0.f, 0.f, 0.f, 0.f};

    for (int ri = 0; ri < rows; ri++) {
        float v0 = Db[ri][sl];
        float v1 = Db[ri][sl + 32];
#pragma unroll
        for (int k = 0; k < 4; k++) {
            int gi = ri - tb - k;
            if (gi >= 0 && gi < nG) {
                float w = Gs[gi];
                acc0[k] = fmaf(v0, w, acc0[k]);
                acc1[k] = fmaf(v1, w, acc1[k]);
            }
        }
    }

    *(float4*)&out[(size_t)(s0 + sl) * T_DIM + t0 + tb] =
        make_float4(acc0[0], acc0[1], acc0[2], acc0[3]);
    *(float4*)&out[(size_t)(s0 + sl + 32) * T_DIM + t0 + tb] =
        make_float4(acc1[0], acc1[1], acc1[2], acc1[3]);
}

// ---------------------------------------------------------------------------
extern "C" void kernel_launch(void* const* d_in, const int* in_sizes, int n_in,
                              void* d_out, int out_size)
{
    const float* x    = (const float*)d_in[0];
    const float* zpos = (const float*)d_in[1];
    const float* mask = (const float*)d_in[2];
    const float* Wp1  = (const float*)d_in[3];
    const float* bp1  = (const float*)d_in[4];
    const float* Wp2  = (const float*)d_in[5];
    const float* bp2  = (const float*)d_in[6];
    const float* Wa1  = (const float*)d_in[7];
    const float* ba1  = (const float*)d_in[8];
    const float* Wa2  = (const float*)d_in[9];
    const float* ba2  = (const float*)d_in[10];
    const float* sig  = (const float*)d_in[11];

    int ne = in_sizes[1];
    if (ne > NE_MAX) ne = NE_MAX;
    int ntiles = (ne + 127) / 128;

    const int dyn_bytes = 6 * BTILE;   // 2 A tiles + 4 B tiles = 208896 B
    cudaFuncSetAttribute(mlp_mma_kernel,
                         cudaFuncAttributeMaxDynamicSharedMemorySize, dyn_bytes);

    prep_kernel<<<dim3(NSTILE, 4), 256>>>(Wp2, Wa2);
    prepH_kernel<<<dim3(ntiles, 2), 256>>>(x, Wp1, bp1, Wa1, ba1, ne);
    bucket_kernel<<<NBUCKET, 256>>>(zpos, ne);

    mlp_mma_kernel<<<dim3(NSTILE, EGRP), 512, dyn_bytes>>>(mask, bp2, ba2, ne);

    stageA_kernel<<<dim3(S_DIM / 128, NBUCKET), 256>>>();

    conv_kernel<<<dim3(S_DIM / 64, T_DIM / 32), 256>>>(sig, (float*)d_out);
}

// round 12
// speedup vs baseline: 1.5665x; 1.0555x over previous
#include <cuda_runtime.h>
#include <cuda_bf16.h>
#include <math.h>
#include <stdint.h>

#define S_DIM 1024
#define T_DIM 1024
#define HID_DIM 128
#define NE_MAX 32000
#define NETILES 250          // ceil(NE_MAX/128)
#define NBUCKET 33
#define BWID 32              // bucket width in tap columns
#define BCAP 2048
#define RMAX 72
#define NSTILE 8
#define EGRP 18
#define BTILE 34816u         // one [128][136] bf16 tile in bytes
#define LDT 136              // padded row length (bf16 elems)
#define LDB (LDT * 2)        // row bytes = 272

// ---------------- scratch (__device__ globals) ----------------
__device__ __align__(16) __nv_bfloat16 g_respb[(size_t)NE_MAX * S_DIM];     // [e][s]
__device__ __align__(16) float g_D[(size_t)NBUCKET * BWID * S_DIM];         // [c][s]
__device__ int   g_bcnt[NBUCKET];
__device__ int   g_bidx[NBUCKET * BCAP];
__device__ float g_bz[NBUCKET * BCAP];
// bf16 weight tiles [stile][p_hi,p_lo,a_hi,a_lo][128k][136n]
__device__ __align__(16) unsigned char g_Bprep[(size_t)NSTILE * 4 * BTILE];
// precomputed hidden activations [etile][p,a][128el][LDT k]
__device__ __align__(16) unsigned char g_Hprep[(size_t)NETILES * 2 * BTILE];

// ---------------- helpers ----------------
__device__ __forceinline__ uint32_t smem_u32(const void* p) {
    uint32_t a;
    asm("{ .reg .u64 t; cvta.to.shared.u64 t, %1; cvt.u32.u64 %0, t; }"
        : "=r"(a) : "l"(p));
    return a;
}
__device__ __forceinline__ void ldsm_x4(uint32_t* r, uint32_t addr) {
    asm volatile("ldmatrix.sync.aligned.m8n8.x4.shared.b16 {%0,%1,%2,%3}, [%4];"
                 : "=r"(r[0]), "=r"(r[1]), "=r"(r[2]), "=r"(r[3]) : "r"(addr));
}
__device__ __forceinline__ void ldsm_x4_t(uint32_t* r, uint32_t addr) {
    asm volatile("ldmatrix.sync.aligned.m8n8.x4.trans.shared.b16 {%0,%1,%2,%3}, [%4];"
                 : "=r"(r[0]), "=r"(r[1]), "=r"(r[2]), "=r"(r[3]) : "r"(addr));
}
__device__ __forceinline__ void mma_bf16(float* c, const uint32_t* a, const uint32_t* b) {
    asm volatile("mma.sync.aligned.m16n8k16.row.col.f32.bf16.bf16.f32 "
                 "{%0,%1,%2,%3}, {%4,%5,%6,%7}, {%8,%9}, {%0,%1,%2,%3};"
                 : "+f"(c[0]), "+f"(c[1]), "+f"(c[2]), "+f"(c[3])
                 : "r"(a[0]), "r"(a[1]), "r"(a[2]), "r"(a[3]), "r"(b[0]), "r"(b[1]));
}

// ---------------------------------------------------------------------------
// Prep: split W2 into bf16 hi/lo tiles [k][136] row-major.
// which: 0=p_hi 1=p_lo 2=a_hi 3=a_lo
// ---------------------------------------------------------------------------
__global__ void prep_kernel(const float* __restrict__ Wp2, const float* __restrict__ Wa2)
{
    const int stile = blockIdx.x, which = blockIdx.y;
    const int s0 = stile * 128;
    const float* W2 = (which >= 2) ? Wa2 : Wp2;
    const int split = which & 1;
    __nv_bfloat16* dst = (__nv_bfloat16*)(g_Bprep + ((size_t)stile * 4 + which) * BTILE);
    for (int idx = threadIdx.x; idx < 128 * 128; idx += 256) {
        int k = idx >> 7, n = idx & 127;
        float w = W2[(size_t)k * S_DIM + s0 + n];
        __nv_bfloat16 hi = __float2bfloat16(w);
        __nv_bfloat16 v = split ? __float2bfloat16(w - __bfloat162float(hi)) : hi;
        dst[k * LDT + n] = v;
    }
}

// ---------------------------------------------------------------------------
// PrepH: hidden layer H = relu(x@W1+b1) as bf16 A-tiles [el][k], stride LDT.
// ---------------------------------------------------------------------------
__global__ void prepH_kernel(const float* __restrict__ x,
                             const float* __restrict__ Wp1, const float* __restrict__ bp1,
                             const float* __restrict__ Wa1, const float* __restrict__ ba1,
                             int ne)
{
    const int tile = blockIdx.x, m = blockIdx.y;
    const int tid = threadIdx.x;
    const int e0 = tile * 128;

    __shared__ __align__(16) float xs[128][3];
    __shared__ __align__(16) float W1s[3][HID_DIM];
    __shared__ __align__(16) float b1s[HID_DIM];

    const float* W1 = m ? Wa1 : Wp1;
    const float* b1 = m ? ba1 : bp1;
    for (int i = tid; i < 3 * HID_DIM; i += 256) (&W1s[0][0])[i] = W1[i];
    if (tid < HID_DIM) b1s[tid] = b1[tid];
    if (tid < 128) {
        int e = e0 + tid;
        if (e < ne) {
            xs[tid][0] = x[e * 3 + 0];
            xs[tid][1] = x[e * 3 + 1];
            xs[tid][2] = x[e * 3 + 2];
        } else {
            xs[tid][0] = 0.f; xs[tid][1] = 0.f; xs[tid][2] = 0.f;
        }
    }
    __syncthreads();

    unsigned char* dst = g_Hprep + ((size_t)tile * 2 + m) * BTILE;
    for (int i = tid; i < 8192; i += 256) {
        int el = i >> 6, k = (i & 63) * 2;
        float x0 = xs[el][0], x1 = xs[el][1], x2 = xs[el][2];
        float h0 = b1s[k]     + x0 * W1s[0][k]     + x1 * W1s[1][k]     + x2 * W1s[2][k];
        float h1 = b1s[k + 1] + x0 * W1s[0][k + 1] + x1 * W1s[1][k + 1] + x2 * W1s[2][k + 1];
        h0 = fmaxf(h0, 0.f); h1 = fmaxf(h1, 0.f);
        __nv_bfloat162 v = __floats2bfloat162_rn(h0, h1);
        *(uint32_t*)(dst + el * LDB + k * 2) = *(uint32_t*)&v;
    }
}

// ---------------------------------------------------------------------------
// Bucket electrons (deterministic, index order), 4 per thread per round.
// Bucket b holds electrons with k=floor(z) in [32b-5, 32b+31].
// ---------------------------------------------------------------------------
__global__ void bucket_kernel(const float* __restrict__ zpos, int ne)
{
    const int b = blockIdx.x;
    const int tid = threadIdx.x;
    const float lob = (float)(b * BWID - 5);
    const float hib = (float)(b * BWID + BWID);

    __shared__ int wsum[4][8];
    __shared__ int base0;
    if (tid == 0) base0 = 0;
    __syncthreads();

    const int lane = tid & 31, w = tid >> 5;
    for (int cb = 0; cb < ne; cb += 1024) {
        float z[4]; bool kp[4]; unsigned bm[4];
#pragma unroll
        for (int q = 0; q < 4; q++) {
            int e = cb + q * 256 + tid;
            kp[q] = false; z[q] = 0.f;
            if (e < ne) { z[q] = zpos[e]; kp[q] = (z[q] >= lob) && (z[q] < hib); }
        }
#pragma unroll
        for (int q = 0; q < 4; q++) bm[q] = __ballot_sync(0xffffffffu, kp[q]);
        if (lane == 0)
#pragma unroll
            for (int q = 0; q < 4; q++) wsum[q][w] = __popc(bm[q]);
        __syncthreads();
        if (tid == 0) {
            int run = base0;
#pragma unroll
            for (int q = 0; q < 4; q++)
#pragma unroll
                for (int ww = 0; ww < 8; ww++) {
                    int t = wsum[q][ww]; wsum[q][ww] = run; run += t;
                }
            base0 = run;
        }
        __syncthreads();
#pragma unroll
        for (int q = 0; q < 4; q++) {
            if (kp[q]) {
                int p = wsum[q][w] + __popc(bm[q] & ((1u << lane) - 1u));
                if (p < BCAP) {
                    g_bidx[b * BCAP + p] = cb + q * 256 + tid;
                    g_bz[b * BCAP + p] = z[q];
                }
            }
        }
        __syncthreads();
    }
    if (tid == 0) g_bcnt[b] = (base0 < BCAP) ? base0 : BCAP;
}

// ---------------------------------------------------------------------------
// MLP via mma.sync bf16 with exact hi/lo weight split.
// Grid (NSTILE=8, EGRP=18), 512 threads / 16 warps = 4(M32) x 4(N32).
// A fragments reused across hi/lo splits; 12 ldsm per 32 mma per k-step.
// ---------------------------------------------------------------------------
__global__ __launch_bounds__(512, 1)
void mlp_mma_kernel(const float* __restrict__ maskv,
                    const float* __restrict__ bp2, const float* __restrict__ ba2,
                    int ne)
{
    extern __shared__ __align__(16) unsigned char dyn[];
    __shared__ __align__(16) float bb[2][128];

    const int tid = threadIdx.x;
    const int wid = tid >> 5, lane = tid & 31;
    const int wm = wid >> 2;          // 0..3 over electrons (32 each)
    const int wn = wid & 3;           // 0..3 over sensors (32 each)
    const int stile = blockIdx.x, gy = blockIdx.y;
    const int s0 = stile * 128;
    const int ntiles = (ne + 127) / 128;

    unsigned char* Ap = dyn;                 // [128][LDT] bf16, prob H
    unsigned char* Aa = dyn + BTILE;         // amp H
    unsigned char* Bt = dyn + 2 * BTILE;     // 4 weight tiles: p_hi,p_lo,a_hi,a_lo

    if (tid < 128) {
        bb[0][tid] = bp2[s0 + tid];
        bb[1][tid] = ba2[s0 + tid];
    }
    {
        const uint4* src = (const uint4*)(g_Bprep + (size_t)stile * 4 * BTILE);
        uint4* d4 = (uint4*)Bt;
        for (int i = tid; i < (int)(4 * BTILE / 16); i += 512) d4[i] = src[i];
    }
    __syncthreads();

    const uint32_t ApS = smem_u32(Ap), AaS = smem_u32(Aa), BtS = smem_u32(Bt);
    const uint32_t lmOff = (uint32_t)(lane & 15) * LDB + (uint32_t)(lane >> 4) * 16;

    for (int et = gy; et < ntiles; et += EGRP) {
        const int e0 = et * 128;

        __syncthreads();   // all warps done reading previous A tiles
        {
            const uint4* asrc = (const uint4*)(g_Hprep + (size_t)et * 2 * BTILE);
            uint4* ad = (uint4*)Ap;          // Ap,Aa contiguous: 4352 uint4
            for (int i = tid; i < 4352; i += 512) ad[i] = asrc[i];
        }
        __syncthreads();

        float accP[2][4][4], accA[2][4][4];
#pragma unroll
        for (int mc = 0; mc < 2; mc++)
#pragma unroll
            for (int nc = 0; nc < 4; nc++)
#pragma unroll
                for (int j = 0; j < 4; j++) { accP[mc][nc][j] = 0.f; accA[mc][nc][j] = 0.f; }

        const uint32_t aRow0 = (uint32_t)(wm * 32) * LDB + lmOff;
        const uint32_t aRow1 = (uint32_t)(wm * 32 + 16) * LDB + lmOff;
        const uint32_t bCol0 = (uint32_t)(wn * 32) * 2 + lmOff;
        const uint32_t bCol1 = (uint32_t)(wn * 32 + 16) * 2 + lmOff;

#pragma unroll
        for (int ks = 0; ks < 8; ks++) {
            const uint32_t kb = (uint32_t)ks * 32;
            const uint32_t krow = (uint32_t)ks * 16 * LDB;
            uint32_t a0[4], a1[4], b0[4], b1[4];

            // ======== prob MLP: A loaded once, hi+lo B ========
            ldsm_x4(a0, ApS + aRow0 + kb);
            ldsm_x4(a1, ApS + aRow1 + kb);
            // hi
            ldsm_x4_t(b0, BtS + krow + bCol0);
            ldsm_x4_t(b1, BtS + krow + bCol1);
            mma_bf16(accP[0][0], a0, &b0[0]); mma_bf16(accP[0][1], a0, &b0[2]);
            mma_bf16(accP[0][2], a0, &b1[0]); mma_bf16(accP[0][3], a0, &b1[2]);
            mma_bf16(accP[1][0], a1, &b0[0]); mma_bf16(accP[1][1], a1, &b0[2]);
            mma_bf16(accP[1][2], a1, &b1[0]); mma_bf16(accP[1][3], a1, &b1[2]);
            // lo
            ldsm_x4_t(b0, BtS + BTILE + krow + bCol0);
            ldsm_x4_t(b1, BtS + BTILE + krow + bCol1);
            mma_bf16(accP[0][0], a0, &b0[0]); mma_bf16(accP[0][1], a0, &b0[2]);
            mma_bf16(accP[0][2], a0, &b1[0]); mma_bf16(accP[0][3], a0, &b1[2]);
            mma_bf16(accP[1][0], a1, &b0[0]); mma_bf16(accP[1][1], a1, &b0[2]);
            mma_bf16(accP[1][2], a1, &b1[0]); mma_bf16(accP[1][3], a1, &b1[2]);

            // ======== amp MLP ========
            ldsm_x4(a0, AaS + aRow0 + kb);
            ldsm_x4(a1, AaS + aRow1 + kb);
            // hi
            ldsm_x4_t(b0, BtS + 2 * BTILE + krow + bCol0);
            ldsm_x4_t(b1, BtS + 2 * BTILE + krow + bCol1);
            mma_bf16(accA[0][0], a0, &b0[0]); mma_bf16(accA[0][1], a0, &b0[2]);
            mma_bf16(accA[0][2], a0, &b1[0]); mma_bf16(accA[0][3], a0, &b1[2]);
            mma_bf16(accA[1][0], a1, &b0[0]); mma_bf16(accA[1][1], a1, &b0[2]);
            mma_bf16(accA[1][2], a1, &b1[0]); mma_bf16(accA[1][3], a1, &b1[2]);
            // lo
            ldsm_x4_t(b0, BtS + 3 * BTILE + krow + bCol0);
            ldsm_x4_t(b1, BtS + 3 * BTILE + krow + bCol1);
            mma_bf16(accA[0][0], a0, &b0[0]); mma_bf16(accA[0][1], a0, &b0[2]);
            mma_bf16(accA[0][2], a0, &b1[0]); mma_bf16(accA[0][3], a0, &b1[2]);
            mma_bf16(accA[1][0], a1, &b0[0]); mma_bf16(accA[1][1], a1, &b0[2]);
            mma_bf16(accA[1][2], a1, &b1[0]); mma_bf16(accA[1][3], a1, &b1[2]);
        }

        // epilogue: fused bias+sigmoid+amp+mask, bf16 stores
#pragma unroll
        for (int mc = 0; mc < 2; mc++) {
            int ra = e0 + wm * 32 + mc * 16 + (lane >> 2);
            int rb = ra + 8;
            float mka = (ra < ne) ? maskv[ra] : 0.f;
            float mkb = (rb < ne) ? maskv[rb] : 0.f;
#pragma unroll
            for (int nc = 0; nc < 4; nc++) {
                int col = wn * 32 + nc * 8 + (lane & 3) * 2;
                float bp0 = bb[0][col], bp1v = bb[0][col + 1];
                float ba0 = bb[1][col], ba1v = bb[1][col + 1];
                float p0 = accP[mc][nc][0] + bp0, p1 = accP[mc][nc][1] + bp1v;
                float p2 = accP[mc][nc][2] + bp0, p3 = accP[mc][nc][3] + bp1v;
                float A0 = accA[mc][nc][0] + ba0, A1 = accA[mc][nc][1] + ba1v;
                float A2 = accA[mc][nc][2] + ba0, A3 = accA[mc][nc][3] + ba1v;
                float o0 = A0 * mka * (1.0f / (1.0f + expf(-p0)));
                float o1 = A1 * mka * (1.0f / (1.0f + expf(-p1)));
                float o2 = A2 * mkb * (1.0f / (1.0f + expf(-p2)));
                float o3 = A3 * mkb * (1.0f / (1.0f + expf(-p3)));
                if (ra < ne) *(__nv_bfloat162*)&g_respb[(size_t)ra * S_DIM + s0 + col] =
                    __floats2bfloat162_rn(o0, o1);
                if (rb < ne) *(__nv_bfloat162*)&g_respb[(size_t)rb * S_DIM + s0 + col] =
                    __floats2bfloat162_rn(o2, o3);
            }
        }
    }
}

// ---------------------------------------------------------------------------
// Stage A as dense GEMM per bucket: D[32, s] = W[32, e] @ resp[e, s].
// W[c,e] = lagrange6 tap weight (bf16, built in smem per 128-electron chunk).
// grid (8 s-tiles of 128, 33 buckets), 256 threads / 8 warps = 2(M16) x 4(N32).
// ---------------------------------------------------------------------------
__global__ __launch_bounds__(256)
void stageA_kernel()
{
    const int s0 = blockIdx.x * 128;
    const int b = blockIdx.y;
    const int tid = threadIdx.x;
    const int wid = tid >> 5, lane = tid & 31;
    const int wm = wid >> 2;          // 0..1 (16 tap rows each)
    const int wn = wid & 3;           // 0..3 (32 sensors each)

    __shared__ __align__(16) unsigned char Wt[32 * LDB];      // [32 c][136 e] bf16
    __shared__ __align__(16) unsigned char Rt[128 * LDB];     // [128 e][136 s] bf16
    __shared__ int ech[128];

    const int cnt = g_bcnt[b];
    const int c0 = b * BWID;

    float acc[4][4];
#pragma unroll
    for (int nt = 0; nt < 4; nt++)
#pragma unroll
        for (int j = 0; j < 4; j++) acc[nt][j] = 0.f;

    const uint32_t WtS = smem_u32(Wt), RtS = smem_u32(Rt);
    const uint32_t lmOff = (uint32_t)(lane & 15) * LDB + (uint32_t)(lane >> 4) * 16;

    for (int base = 0; base < cnt; base += 128) {
        int n = cnt - base; if (n > 128) n = 128;

        float z = 0.f; int eidx = 0;
        if (tid < n) {
            z = g_bz[b * BCAP + base + tid];
            eidx = g_bidx[b * BCAP + base + tid];
        }

        for (int i = tid; i < 32 * LDB / 4; i += 256) ((uint32_t*)Wt)[i] = 0u;
        if (tid < n) ech[tid] = eidx;
        __syncthreads();

        if (tid < n) {
            float kf = floorf(z);
            float f = z - kf;
            int kl = (int)kf - c0;                 // in [-5, 31]
            float t0 = f + 2.f, t1 = f + 1.f, t2 = f, t3 = f - 1.f,
                  t4 = f - 2.f, t5 = f - 3.f;
            float w[6];
            w[0] = t1 * t2 * t3 * t4 * t5 * (-1.f / 120.f);
            w[1] = t0 * t2 * t3 * t4 * t5 * ( 1.f /  24.f);
            w[2] = t0 * t1 * t3 * t4 * t5 * (-1.f /  12.f);
            w[3] = t0 * t1 * t2 * t4 * t5 * ( 1.f /  12.f);
            w[4] = t0 * t1 * t2 * t3 * t5 * (-1.f /  24.f);
            w[5] = t0 * t1 * t2 * t3 * t4 * ( 1.f / 120.f);
#pragma unroll
            for (int j = 0; j < 6; j++) {
                int c = kl + j;
                if (c >= 0 && c < 32)
                    *(__nv_bfloat16*)(Wt + c * LDB + tid * 2) = __float2bfloat16(w[j]);
            }
        }

        for (int i = tid; i < n * 16; i += 256) {
            int e = i >> 4, q = i & 15;
            ((uint4*)(Rt + e * LDB))[q] =
                ((const uint4*)&g_respb[(size_t)ech[e] * S_DIM + s0])[q];
        }
        __syncthreads();

#pragma unroll
        for (int ks = 0; ks < 8; ks++) {
            uint32_t a0[4], bf[2][4];
            ldsm_x4(a0, WtS + (uint32_t)(wm * 16) * LDB + (uint32_t)ks * 32 + lmOff);
#pragma unroll
            for (int nb = 0; nb < 2; nb++)
                ldsm_x4_t(bf[nb], RtS + (uint32_t)(ks * 16) * LDB +
                                  (uint32_t)(wn * 32 + nb * 16) * 2 + lmOff);
#pragma unroll
            for (int nb = 0; nb < 2; nb++) {
                mma_bf16(acc[2 * nb],     a0, &bf[nb][0]);
                mma_bf16(acc[2 * nb + 1], a0, &bf[nb][2]);
            }
        }
        __syncthreads();
    }

    const int r0 = c0 + wm * 16 + (lane >> 2);
    const int colb = s0 + wn * 32 + (lane & 3) * 2;
#pragma unroll
    for (int nt = 0; nt < 4; nt++) {
        int col = colb + nt * 8;
        *(float2*)&g_D[(size_t)r0 * S_DIM + col] = make_float2(acc[nt][0], acc[nt][1]);
        *(float2*)&g_D[(size_t)(r0 + 8) * S_DIM + col] = make_float2(acc[nt][2], acc[nt][3]);
    }
}

// ---------------------------------------------------------------------------
// Banded 1-D convolution out[s,t] = sum_tau D[tau+2,s] * G(t-tau).
// ---------------------------------------------------------------------------
__global__ __launch_bounds__(256)
void conv_kernel(const float* __restrict__ sig, float* __restrict__ out)
{
    __shared__ float Db[2 * RMAX + 33][64];
    __shared__ float Gs[2 * RMAX + 1];

    const int s0 = blockIdx.x * 64;
    const int t0 = blockIdx.y * 32;
    const int tid = threadIdx.x;

    const float sigma  = sig[0];
    const float inv2s2 = 1.0f / (2.0f * sigma * sigma);
    const float coef   = 0.3989422804f / sqrtf(sigma * sigma);
    int R = (int)ceilf(sigma * 7.746f);
    if (R < 1) R = 1;
    if (R > RMAX) R = RMAX;
    const int nG = 2 * R + 1;
    const int rows = 2 * R + 33;
    const int rlo = t0 - R + 2;

    for (int i = tid; i < nG; i += 256) {
        float d = (float)(i - R);
        Gs[i] = coef * expf(-d * d * inv2s2);
    }
    for (int idx = tid; idx < rows * 64; idx += 256) {
        int ri = idx >> 6, s2 = idx & 63;
        int c = rlo + ri;
        Db[ri][s2] = (c >= 0 && c < T_DIM + 4) ?
            g_D[(size_t)c * S_DIM + s0 + s2] : 0.f;
    }
    __syncthreads();

    const int sl = tid & 31;
    const int tq = tid >> 5;
    const int tb = tq * 4;

    float acc0[4] = {0.f, 0.f, 0.f, 0.f};
    float acc1[4] = {0.f, 0.f, 0.f, 0.f};

    for (int ri = 0; ri < rows; ri++) {
        float v0 = Db[ri][sl];
        float v1 = Db[ri][sl + 32];
#pragma unroll
        for (int k = 0; k < 4; k++) {
            int gi = ri - tb - k;
            if (gi >= 0 && gi < nG) {
                float w = Gs[gi];
                acc0[k] = fmaf(v0, w, acc0[k]);
                acc1[k] = fmaf(v1, w, acc1[k]);
            }
        }
    }

    *(float4*)&out[(size_t)(s0 + sl) * T_DIM + t0 + tb] =
        make_float4(acc0[0], acc0[1], acc0[2], acc0[3]);
    *(float4*)&out[(size_t)(s0 + sl + 32) * T_DIM + t0 + tb] =
        make_float4(acc1[0], acc1[1], acc1[2], acc1[3]);
}

// ---------------------------------------------------------------------------
extern "C" void kernel_launch(void* const* d_in, const int* in_sizes, int n_in,
                              void* d_out, int out_size)
{
    const float* x    = (const float*)d_in[0];
    const float* zpos = (const float*)d_in[1];
    const float* mask = (const float*)d_in[2];
    const float* Wp1  = (const float*)d_in[3];
    const float* bp1  = (const float*)d_in[4];
    const float* Wp2  = (const float*)d_in[5];
    const float* bp2  = (const float*)d_in[6];
    const float* Wa1  = (const float*)d_in[7];
    const float* ba1  = (const float*)d_in[8];
    const float* Wa2  = (const float*)d_in[9];
    const float* ba2  = (const float*)d_in[10];
    const float* sig  = (const float*)d_in[11];

    int ne = in_sizes[1];
    if (ne > NE_MAX) ne = NE_MAX;
    int ntiles = (ne + 127) / 128;

    const int dyn_bytes = 6 * BTILE;   // 2 A tiles + 4 B tiles = 208896 B
    cudaFuncSetAttribute(mlp_mma_kernel,
                         cudaFuncAttributeMaxDynamicSharedMemorySize, dyn_bytes);

    prep_kernel<<<dim3(NSTILE, 4), 256>>>(Wp2, Wa2);
    prepH_kernel<<<dim3(ntiles, 2), 256>>>(x, Wp1, bp1, Wa1, ba1, ne);
    bucket_kernel<<<NBUCKET, 256>>>(zpos, ne);

    mlp_mma_kernel<<<dim3(NSTILE, EGRP), 512, dyn_bytes>>>(mask, bp2, ba2, ne);

    stageA_kernel<<<dim3(S_DIM / 128, NBUCKET), 256>>>();

    conv_kernel<<<dim3(S_DIM / 64, T_DIM / 32), 256>>>(sig, (float*)d_out);
}

// round 13
// speedup vs baseline: 1.8301x; 1.1683x over previous
#include <cuda_runtime.h>
#include <cuda_fp16.h>
#include <math.h>
#include <stdint.h>

#define S_DIM 1024
#define T_DIM 1024
#define HID_DIM 128
#define NE_MAX 32000
#define NETILES 250          // ceil(NE_MAX/128)
#define NBUCKET 33
#define BWID 32              // bucket width in tap columns
#define BCAP 2048
#define RMAX 72
#define NSTILE 8
#define EGRP 18
#define BTILE 34816u         // one [128][136] fp16 tile in bytes
#define LDT 136              // padded row length (fp16 elems)
#define LDB (LDT * 2)        // row bytes = 272

// ---------------- scratch (__device__ globals) ----------------
__device__ __align__(16) __half g_resph[(size_t)NE_MAX * S_DIM];            // [e][s]
__device__ __align__(16) float g_D[(size_t)NBUCKET * BWID * S_DIM];         // [c][s]
__device__ int   g_bcnt[NBUCKET];
__device__ int   g_bidx[NBUCKET * BCAP];
__device__ float g_bz[NBUCKET * BCAP];
// fp16 weight tiles [stile][p,a][128k][136n]
__device__ __align__(16) unsigned char g_Bprep[(size_t)NSTILE * 2 * BTILE];
// precomputed hidden activations [etile][p,a][128el][LDT k]
__device__ __align__(16) unsigned char g_Hprep[(size_t)NETILES * 2 * BTILE];

// ---------------- helpers ----------------
__device__ __forceinline__ uint32_t smem_u32(const void* p) {
    uint32_t a;
    asm("{ .reg .u64 t; cvta.to.shared.u64 t, %1; cvt.u32.u64 %0, t; }"
        : "=r"(a) : "l"(p));
    return a;
}
__device__ __forceinline__ void ldsm_x4(uint32_t* r, uint32_t addr) {
    asm volatile("ldmatrix.sync.aligned.m8n8.x4.shared.b16 {%0,%1,%2,%3}, [%4];"
                 : "=r"(r[0]), "=r"(r[1]), "=r"(r[2]), "=r"(r[3]) : "r"(addr));
}
__device__ __forceinline__ void ldsm_x4_t(uint32_t* r, uint32_t addr) {
    asm volatile("ldmatrix.sync.aligned.m8n8.x4.trans.shared.b16 {%0,%1,%2,%3}, [%4];"
                 : "=r"(r[0]), "=r"(r[1]), "=r"(r[2]), "=r"(r[3]) : "r"(addr));
}
__device__ __forceinline__ void mma_f16(float* c, const uint32_t* a, const uint32_t* b) {
    asm volatile("mma.sync.aligned.m16n8k16.row.col.f32.f16.f16.f32 "
                 "{%0,%1,%2,%3}, {%4,%5,%6,%7}, {%8,%9}, {%0,%1,%2,%3};"
                 : "+f"(c[0]), "+f"(c[1]), "+f"(c[2]), "+f"(c[3])
                 : "r"(a[0]), "r"(a[1]), "r"(a[2]), "r"(a[3]), "r"(b[0]), "r"(b[1]));
}

// ---------------------------------------------------------------------------
// Prep: W2 as fp16 tiles [k][136] row-major. grid (NSTILE, 2): y=0 prob, 1 amp.
// ---------------------------------------------------------------------------
__global__ void prep_kernel(const float* __restrict__ Wp2, const float* __restrict__ Wa2)
{
    const int stile = blockIdx.x, m = blockIdx.y;
    const int s0 = stile * 128;
    const float* W2 = m ? Wa2 : Wp2;
    __half* dst = (__half*)(g_Bprep + ((size_t)stile * 2 + m) * BTILE);
    for (int idx = threadIdx.x; idx < 128 * 128; idx += 256) {
        int k = idx >> 7, n = idx & 127;
        dst[k * LDT + n] = __float2half_rn(W2[(size_t)k * S_DIM + s0 + n]);
    }
}

// ---------------------------------------------------------------------------
// PrepH: hidden layer H = relu(x@W1+b1) as fp16 A-tiles [el][k], stride LDT.
// ---------------------------------------------------------------------------
__global__ void prepH_kernel(const float* __restrict__ x,
                             const float* __restrict__ Wp1, const float* __restrict__ bp1,
                             const float* __restrict__ Wa1, const float* __restrict__ ba1,
                             int ne)
{
    const int tile = blockIdx.x, m = blockIdx.y;
    const int tid = threadIdx.x;
    const int e0 = tile * 128;

    __shared__ __align__(16) float xs[128][3];
    __shared__ __align__(16) float W1s[3][HID_DIM];
    __shared__ __align__(16) float b1s[HID_DIM];

    const float* W1 = m ? Wa1 : Wp1;
    const float* b1 = m ? ba1 : bp1;
    for (int i = tid; i < 3 * HID_DIM; i += 256) (&W1s[0][0])[i] = W1[i];
    if (tid < HID_DIM) b1s[tid] = b1[tid];
    if (tid < 128) {
        int e = e0 + tid;
        if (e < ne) {
            xs[tid][0] = x[e * 3 + 0];
            xs[tid][1] = x[e * 3 + 1];
            xs[tid][2] = x[e * 3 + 2];
        } else {
            xs[tid][0] = 0.f; xs[tid][1] = 0.f; xs[tid][2] = 0.f;
        }
    }
    __syncthreads();

    unsigned char* dst = g_Hprep + ((size_t)tile * 2 + m) * BTILE;
    for (int i = tid; i < 8192; i += 256) {
        int el = i >> 6, k = (i & 63) * 2;
        float x0 = xs[el][0], x1 = xs[el][1], x2 = xs[el][2];
        float h0 = b1s[k]     + x0 * W1s[0][k]     + x1 * W1s[1][k]     + x2 * W1s[2][k];
        float h1 = b1s[k + 1] + x0 * W1s[0][k + 1] + x1 * W1s[1][k + 1] + x2 * W1s[2][k + 1];
        h0 = fmaxf(h0, 0.f); h1 = fmaxf(h1, 0.f);
        __half2 v = __floats2half2_rn(h0, h1);
        *(uint32_t*)(dst + el * LDB + k * 2) = *(uint32_t*)&v;
    }
}

// ---------------------------------------------------------------------------
// Bucket electrons (deterministic, index order), 4 per thread per round.
// Bucket b holds electrons with k=floor(z) in [32b-5, 32b+31].
// ---------------------------------------------------------------------------
__global__ void bucket_kernel(const float* __restrict__ zpos, int ne)
{
    const int b = blockIdx.x;
    const int tid = threadIdx.x;
    const float lob = (float)(b * BWID - 5);
    const float hib = (float)(b * BWID + BWID);

    __shared__ int wsum[4][8];
    __shared__ int base0;
    if (tid == 0) base0 = 0;
    __syncthreads();

    const int lane = tid & 31, w = tid >> 5;
    for (int cb = 0; cb < ne; cb += 1024) {
        float z[4]; bool kp[4]; unsigned bm[4];
#pragma unroll
        for (int q = 0; q < 4; q++) {
            int e = cb + q * 256 + tid;
            kp[q] = false; z[q] = 0.f;
            if (e < ne) { z[q] = zpos[e]; kp[q] = (z[q] >= lob) && (z[q] < hib); }
        }
#pragma unroll
        for (int q = 0; q < 4; q++) bm[q] = __ballot_sync(0xffffffffu, kp[q]);
        if (lane == 0)
#pragma unroll
            for (int q = 0; q < 4; q++) wsum[q][w] = __popc(bm[q]);
        __syncthreads();
        if (tid == 0) {
            int run = base0;
#pragma unroll
            for (int q = 0; q < 4; q++)
#pragma unroll
                for (int ww = 0; ww < 8; ww++) {
                    int t = wsum[q][ww]; wsum[q][ww] = run; run += t;
                }
            base0 = run;
        }
        __syncthreads();
#pragma unroll
        for (int q = 0; q < 4; q++) {
            if (kp[q]) {
                int p = wsum[q][w] + __popc(bm[q] & ((1u << lane) - 1u));
                if (p < BCAP) {
                    g_bidx[b * BCAP + p] = cb + q * 256 + tid;
                    g_bz[b * BCAP + p] = z[q];
                }
            }
        }
        __syncthreads();
    }
    if (tid == 0) g_bcnt[b] = (base0 < BCAP) ? base0 : BCAP;
}

// ---------------------------------------------------------------------------
// MLP via mma.sync fp16 (single pass). Grid (NSTILE=8, EGRP=18),
// 512 threads / 16 warps = 4(M32) x 4(N32). B (2 tiles) resident.
// Per k-step: 8 ldsm / 16 mma.
// ---------------------------------------------------------------------------
__global__ __launch_bounds__(512, 1)
void mlp_mma_kernel(const float* __restrict__ maskv,
                    const float* __restrict__ bp2, const float* __restrict__ ba2,
                    int ne)
{
    extern __shared__ __align__(16) unsigned char dyn[];
    __shared__ __align__(16) float bb[2][128];

    const int tid = threadIdx.x;
    const int wid = tid >> 5, lane = tid & 31;
    const int wm = wid >> 2;          // 0..3 over electrons (32 each)
    const int wn = wid & 3;           // 0..3 over sensors (32 each)
    const int stile = blockIdx.x, gy = blockIdx.y;
    const int s0 = stile * 128;
    const int ntiles = (ne + 127) / 128;

    unsigned char* Ap = dyn;                 // [128][LDT] fp16, prob H
    unsigned char* Aa = dyn + BTILE;         // amp H
    unsigned char* Bt = dyn + 2 * BTILE;     // 2 weight tiles: p, a

    if (tid < 128) {
        bb[0][tid] = bp2[s0 + tid];
        bb[1][tid] = ba2[s0 + tid];
    }
    {
        const uint4* src = (const uint4*)(g_Bprep + (size_t)stile * 2 * BTILE);
        uint4* d4 = (uint4*)Bt;
        for (int i = tid; i < (int)(2 * BTILE / 16); i += 512) d4[i] = src[i];
    }
    __syncthreads();

    const uint32_t ApS = smem_u32(Ap), AaS = smem_u32(Aa), BtS = smem_u32(Bt);
    const uint32_t lmOff = (uint32_t)(lane & 15) * LDB + (uint32_t)(lane >> 4) * 16;

    for (int et = gy; et < ntiles; et += EGRP) {
        const int e0 = et * 128;

        __syncthreads();   // all warps done reading previous A tiles
        {
            const uint4* asrc = (const uint4*)(g_Hprep + (size_t)et * 2 * BTILE);
            uint4* ad = (uint4*)Ap;          // Ap,Aa contiguous: 4352 uint4
            for (int i = tid; i < 4352; i += 512) ad[i] = asrc[i];
        }
        __syncthreads();

        float accP[2][4][4], accA[2][4][4];
#pragma unroll
        for (int mc = 0; mc < 2; mc++)
#pragma unroll
            for (int nc = 0; nc < 4; nc++)
#pragma unroll
                for (int j = 0; j < 4; j++) { accP[mc][nc][j] = 0.f; accA[mc][nc][j] = 0.f; }

        const uint32_t aRow0 = (uint32_t)(wm * 32) * LDB + lmOff;
        const uint32_t aRow1 = (uint32_t)(wm * 32 + 16) * LDB + lmOff;
        const uint32_t bCol0 = (uint32_t)(wn * 32) * 2 + lmOff;
        const uint32_t bCol1 = (uint32_t)(wn * 32 + 16) * 2 + lmOff;

#pragma unroll
        for (int ks = 0; ks < 8; ks++) {
            const uint32_t kb = (uint32_t)ks * 32;
            const uint32_t krow = (uint32_t)ks * 16 * LDB;
            uint32_t a0[4], a1[4], b0[4], b1[4];

            // ======== prob MLP ========
            ldsm_x4(a0, ApS + aRow0 + kb);
            ldsm_x4(a1, ApS + aRow1 + kb);
            ldsm_x4_t(b0, BtS + krow + bCol0);
            ldsm_x4_t(b1, BtS + krow + bCol1);
            mma_f16(accP[0][0], a0, &b0[0]); mma_f16(accP[0][1], a0, &b0[2]);
            mma_f16(accP[0][2], a0, &b1[0]); mma_f16(accP[0][3], a0, &b1[2]);
            mma_f16(accP[1][0], a1, &b0[0]); mma_f16(accP[1][1], a1, &b0[2]);
            mma_f16(accP[1][2], a1, &b1[0]); mma_f16(accP[1][3], a1, &b1[2]);

            // ======== amp MLP ========
            ldsm_x4(a0, AaS + aRow0 + kb);
            ldsm_x4(a1, AaS + aRow1 + kb);
            ldsm_x4_t(b0, BtS + BTILE + krow + bCol0);
            ldsm_x4_t(b1, BtS + BTILE + krow + bCol1);
            mma_f16(accA[0][0], a0, &b0[0]); mma_f16(accA[0][1], a0, &b0[2]);
            mma_f16(accA[0][2], a0, &b1[0]); mma_f16(accA[0][3], a0, &b1[2]);
            mma_f16(accA[1][0], a1, &b0[0]); mma_f16(accA[1][1], a1, &b0[2]);
            mma_f16(accA[1][2], a1, &b1[0]); mma_f16(accA[1][3], a1, &b1[2]);
        }

        // epilogue: fused bias+sigmoid+amp+mask, fp16 stores
#pragma unroll
        for (int mc = 0; mc < 2; mc++) {
            int ra = e0 + wm * 32 + mc * 16 + (lane >> 2);
            int rb = ra + 8;
            float mka = (ra < ne) ? maskv[ra] : 0.f;
            float mkb = (rb < ne) ? maskv[rb] : 0.f;
#pragma unroll
            for (int nc = 0; nc < 4; nc++) {
                int col = wn * 32 + nc * 8 + (lane & 3) * 2;
                float bp0 = bb[0][col], bp1v = bb[0][col + 1];
                float ba0 = bb[1][col], ba1v = bb[1][col + 1];
                float p0 = accP[mc][nc][0] + bp0, p1 = accP[mc][nc][1] + bp1v;
                float p2 = accP[mc][nc][2] + bp0, p3 = accP[mc][nc][3] + bp1v;
                float A0 = accA[mc][nc][0] + ba0, A1 = accA[mc][nc][1] + ba1v;
                float A2 = accA[mc][nc][2] + ba0, A3 = accA[mc][nc][3] + ba1v;
                float o0 = A0 * mka * (1.0f / (1.0f + expf(-p0)));
                float o1 = A1 * mka * (1.0f / (1.0f + expf(-p1)));
                float o2 = A2 * mkb * (1.0f / (1.0f + expf(-p2)));
                float o3 = A3 * mkb * (1.0f / (1.0f + expf(-p3)));
                if (ra < ne) *(__half2*)&g_resph[(size_t)ra * S_DIM + s0 + col] =
                    __floats2half2_rn(o0, o1);
                if (rb < ne) *(__half2*)&g_resph[(size_t)rb * S_DIM + s0 + col] =
                    __floats2half2_rn(o2, o3);
            }
        }
    }
}

// ---------------------------------------------------------------------------
// Stage A as dense GEMM per bucket: D[32, s] = W[32, e] @ resp[e, s], fp16.
// grid (8 s-tiles of 128, 33 buckets), 256 threads / 8 warps = 2(M16) x 4(N32).
// ---------------------------------------------------------------------------
__global__ __launch_bounds__(256)
void stageA_kernel()
{
    const int s0 = blockIdx.x * 128;
    const int b = blockIdx.y;
    const int tid = threadIdx.x;
    const int wid = tid >> 5, lane = tid & 31;
    const int wm = wid >> 2;          // 0..1 (16 tap rows each)
    const int wn = wid & 3;           // 0..3 (32 sensors each)

    __shared__ __align__(16) unsigned char Wt[32 * LDB];      // [32 c][136 e] fp16
    __shared__ __align__(16) unsigned char Rt[128 * LDB];     // [128 e][136 s] fp16
    __shared__ int ech[128];

    const int cnt = g_bcnt[b];
    const int c0 = b * BWID;

    float acc[4][4];
#pragma unroll
    for (int nt = 0; nt < 4; nt++)
#pragma unroll
        for (int j = 0; j < 4; j++) acc[nt][j] = 0.f;

    const uint32_t WtS = smem_u32(Wt), RtS = smem_u32(Rt);
    const uint32_t lmOff = (uint32_t)(lane & 15) * LDB + (uint32_t)(lane >> 4) * 16;

    for (int base = 0; base < cnt; base += 128) {
        int n = cnt - base; if (n > 128) n = 128;

        float z = 0.f; int eidx = 0;
        if (tid < n) {
            z = g_bz[b * BCAP + base + tid];
            eidx = g_bidx[b * BCAP + base + tid];
        }

        for (int i = tid; i < 32 * LDB / 4; i += 256) ((uint32_t*)Wt)[i] = 0u;
        if (tid < n) ech[tid] = eidx;
        __syncthreads();

        if (tid < n) {
            float kf = floorf(z);
            float f = z - kf;
            int kl = (int)kf - c0;                 // in [-5, 31]
            float t0 = f + 2.f, t1 = f + 1.f, t2 = f, t3 = f - 1.f,
                  t4 = f - 2.f, t5 = f - 3.f;
            float w[6];
            w[0] = t1 * t2 * t3 * t4 * t5 * (-1.f / 120.f);
            w[1] = t0 * t2 * t3 * t4 * t5 * ( 1.f /  24.f);
            w[2] = t0 * t1 * t3 * t4 * t5 * (-1.f /  12.f);
            w[3] = t0 * t1 * t2 * t4 * t5 * ( 1.f /  12.f);
            w[4] = t0 * t1 * t2 * t3 * t5 * (-1.f /  24.f);
            w[5] = t0 * t1 * t2 * t3 * t4 * ( 1.f / 120.f);
#pragma unroll
            for (int j = 0; j < 6; j++) {
                int c = kl + j;
                if (c >= 0 && c < 32)
                    *(__half*)(Wt + c * LDB + tid * 2) = __float2half_rn(w[j]);
            }
        }

        for (int i = tid; i < n * 16; i += 256) {
            int e = i >> 4, q = i & 15;
            ((uint4*)(Rt + e * LDB))[q] =
                ((const uint4*)&g_resph[(size_t)ech[e] * S_DIM + s0])[q];
        }
        __syncthreads();

#pragma unroll
        for (int ks = 0; ks < 8; ks++) {
            uint32_t a0[4], bf[2][4];
            ldsm_x4(a0, WtS + (uint32_t)(wm * 16) * LDB + (uint32_t)ks * 32 + lmOff);
#pragma unroll
            for (int nb = 0; nb < 2; nb++)
                ldsm_x4_t(bf[nb], RtS + (uint32_t)(ks * 16) * LDB +
                                  (uint32_t)(wn * 32 + nb * 16) * 2 + lmOff);
#pragma unroll
            for (int nb = 0; nb < 2; nb++) {
                mma_f16(acc[2 * nb],     a0, &bf[nb][0]);
                mma_f16(acc[2 * nb + 1], a0, &bf[nb][2]);
            }
        }
        __syncthreads();
    }

    const int r0 = c0 + wm * 16 + (lane >> 2);
    const int colb = s0 + wn * 32 + (lane & 3) * 2;
#pragma unroll
    for (int nt = 0; nt < 4; nt++) {
        int col = colb + nt * 8;
        *(float2*)&g_D[(size_t)r0 * S_DIM + col] = make_float2(acc[nt][0], acc[nt][1]);
        *(float2*)&g_D[(size_t)(r0 + 8) * S_DIM + col] = make_float2(acc[nt][2], acc[nt][3]);
    }
}

// ---------------------------------------------------------------------------
// Banded 1-D convolution out[s,t] = sum_tau D[tau+2,s] * G(t-tau).
// ---------------------------------------------------------------------------
__global__ __launch_bounds__(256)
void conv_kernel(const float* __restrict__ sig, float* __restrict__ out)
{
    __shared__ float Db[2 * RMAX + 33][64];
    __shared__ float Gs[2 * RMAX + 1];

    const int s0 = blockIdx.x * 64;
    const int t0 = blockIdx.y * 32;
    const int tid = threadIdx.x;

    const float sigma  = sig[0];
    const float inv2s2 = 1.0f / (2.0f * sigma * sigma);
    const float coef   = 0.3989422804f / sqrtf(sigma * sigma);
    int R = (int)ceilf(sigma * 7.746f);
    if (R < 1) R = 1;
    if (R > RMAX) R = RMAX;
    const int nG = 2 * R + 1;
    const int rows = 2 * R + 33;
    const int rlo = t0 - R + 2;

    for (int i = tid; i < nG; i += 256) {
        float d = (float)(i - R);
        Gs[i] = coef * expf(-d * d * inv2s2);
    }
    for (int idx = tid; idx < rows * 64; idx += 256) {
        int ri = idx >> 6, s2 = idx & 63;
        int c = rlo + ri;
        Db[ri][s2] = (c >= 0 && c < T_DIM + 4) ?
            g_D[(size_t)c * S_DIM + s0 + s2] : 0.f;
    }
    __syncthreads();

    const int sl = tid & 31;
    const int tq = tid >> 5;
    const int tb = tq * 4;

    float acc0[4] = {0.f, 0.f, 0.f, 0.f};
    float acc1[4] = {0.f, 0.f, 0.f, 0.f};

    for (int ri = 0; ri < rows; ri++) {
        float v0 = Db[ri][sl];
        float v1 = Db[ri][sl + 32];
#pragma unroll
        for (int k = 0; k < 4; k++) {
            int gi = ri - tb - k;
            if (gi >= 0 && gi < nG) {
                float w = Gs[gi];
                acc0[k] = fmaf(v0, w, acc0[k]);
                acc1[k] = fmaf(v1, w, acc1[k]);
            }
        }
    }

    *(float4*)&out[(size_t)(s0 + sl) * T_DIM + t0 + tb] =
        make_float4(acc0[0], acc0[1], acc0[2], acc0[3]);
    *(float4*)&out[(size_t)(s0 + sl + 32) * T_DIM + t0 + tb] =
        make_float4(acc1[0], acc1[1], acc1[2], acc1[3]);
}

// ---------------------------------------------------------------------------
extern "C" void kernel_launch(void* const* d_in, const int* in_sizes, int n_in,
                              void* d_out, int out_size)
{
    const float* x    = (const float*)d_in[0];
    const float* zpos = (const float*)d_in[1];
    const float* mask = (const float*)d_in[2];
    const float* Wp1  = (const float*)d_in[3];
    const float* bp1  = (const float*)d_in[4];
    const float* Wp2  = (const float*)d_in[5];
    const float* bp2  = (const float*)d_in[6];
    const float* Wa1  = (const float*)d_in[7];
    const float* ba1  = (const float*)d_in[8];
    const float* Wa2  = (const float*)d_in[9];
    const float* ba2  = (const float*)d_in[10];
    const float* sig  = (const float*)d_in[11];

    int ne = in_sizes[1];
    if (ne > NE_MAX) ne = NE_MAX;
    int ntiles = (ne + 127) / 128;

    const int dyn_bytes = 4 * BTILE;   // 2 A tiles + 2 B tiles = 139264 B
    cudaFuncSetAttribute(mlp_mma_kernel,
                         cudaFuncAttributeMaxDynamicSharedMemorySize, dyn_bytes);

    prep_kernel<<<dim3(NSTILE, 2), 256>>>(Wp2, Wa2);
    prepH_kernel<<<dim3(ntiles, 2), 256>>>(x, Wp1, bp1, Wa1, ba1, ne);
    bucket_kernel<<<NBUCKET, 256>>>(zpos, ne);

    mlp_mma_kernel<<<dim3(NSTILE, EGRP), 512, dyn_bytes>>>(mask, bp2, ba2, ne);

    stageA_kernel<<<dim3(S_DIM / 128, NBUCKET), 256>>>();

    conv_kernel<<<dim3(S_DIM / 64, T_DIM / 32), 256>>>(sig, (float*)d_out);
}

// round 14
// speedup vs baseline: 1.9820x; 1.0829x over previous
#include <cuda_runtime.h>
#include <cuda_fp16.h>
#include <math.h>
#include <stdint.h>

#define S_DIM 1024
#define T_DIM 1024
#define HID_DIM 128
#define NE_MAX 32000
#define NETILES 250          // ceil(NE_MAX/128)
#define NBUCKET 33
#define BWID 32              // bucket width in tap columns
#define BCAP 2048
#define RMAX 72
#define NSTILE 8
#define EGRP 18
#define BTILE 34816u         // one [128][136] fp16 tile in bytes
#define LDT 136              // padded row length (fp16 elems)
#define LDB (LDT * 2)        // row bytes = 272

// ---------------- scratch (__device__ globals) ----------------
__device__ __align__(16) __half g_resph[(size_t)NE_MAX * S_DIM];            // [e][s]
__device__ __align__(16) float g_D[(size_t)NBUCKET * BWID * S_DIM];         // [c][s]
__device__ int   g_bcnt[NBUCKET];
__device__ int   g_bidx[NBUCKET * BCAP];
__device__ float g_bz[NBUCKET * BCAP];
// fp16 weight tiles [stile][p,a][128k][136n]
__device__ __align__(16) unsigned char g_Bprep[(size_t)NSTILE * 2 * BTILE];
// precomputed hidden activations [etile][p,a][128el][LDT k]
__device__ __align__(16) unsigned char g_Hprep[(size_t)NETILES * 2 * BTILE];

// ---------------- helpers ----------------
__device__ __forceinline__ uint32_t smem_u32(const void* p) {
    uint32_t a;
    asm("{ .reg .u64 t; cvta.to.shared.u64 t, %1; cvt.u32.u64 %0, t; }"
        : "=r"(a) : "l"(p));
    return a;
}
__device__ __forceinline__ void ldsm_x4(uint32_t* r, uint32_t addr) {
    asm volatile("ldmatrix.sync.aligned.m8n8.x4.shared.b16 {%0,%1,%2,%3}, [%4];"
                 : "=r"(r[0]), "=r"(r[1]), "=r"(r[2]), "=r"(r[3]) : "r"(addr));
}
__device__ __forceinline__ void ldsm_x4_t(uint32_t* r, uint32_t addr) {
    asm volatile("ldmatrix.sync.aligned.m8n8.x4.trans.shared.b16 {%0,%1,%2,%3}, [%4];"
                 : "=r"(r[0]), "=r"(r[1]), "=r"(r[2]), "=r"(r[3]) : "r"(addr));
}
__device__ __forceinline__ void mma_f16(float* c, const uint32_t* a, const uint32_t* b) {
    asm volatile("mma.sync.aligned.m16n8k16.row.col.f32.f16.f16.f32 "
                 "{%0,%1,%2,%3}, {%4,%5,%6,%7}, {%8,%9}, {%0,%1,%2,%3};"
                 : "+f"(c[0]), "+f"(c[1]), "+f"(c[2]), "+f"(c[3])
                 : "r"(a[0]), "r"(a[1]), "r"(a[2]), "r"(a[3]), "r"(b[0]), "r"(b[1]));
}
__device__ __forceinline__ void cp_async16(uint32_t saddr, const void* gptr) {
    asm volatile("cp.async.cg.shared.global [%0], [%1], 16;"
                 :: "r"(saddr), "l"(gptr));
}
#define CP_COMMIT() asm volatile("cp.async.commit_group;" ::: "memory")
#define CP_WAIT0()  asm volatile("cp.async.wait_group 0;" ::: "memory")

// ---------------------------------------------------------------------------
// Prep: W2 as fp16 tiles [k][136] row-major. grid (NSTILE, 2): y=0 prob, 1 amp.
// ---------------------------------------------------------------------------
__global__ void prep_kernel(const float* __restrict__ Wp2, const float* __restrict__ Wa2)
{
    const int stile = blockIdx.x, m = blockIdx.y;
    const int s0 = stile * 128;
    const float* W2 = m ? Wa2 : Wp2;
    __half* dst = (__half*)(g_Bprep + ((size_t)stile * 2 + m) * BTILE);
    for (int idx = threadIdx.x; idx < 128 * 128; idx += 256) {
        int k = idx >> 7, n = idx & 127;
        dst[k * LDT + n] = __float2half_rn(W2[(size_t)k * S_DIM + s0 + n]);
    }
}

// ---------------------------------------------------------------------------
// PrepH: hidden layer H = relu(x@W1+b1) as fp16 A-tiles [el][k], stride LDT.
// ---------------------------------------------------------------------------
__global__ void prepH_kernel(const float* __restrict__ x,
                             const float* __restrict__ Wp1, const float* __restrict__ bp1,
                             const float* __restrict__ Wa1, const float* __restrict__ ba1,
                             int ne)
{
    const int tile = blockIdx.x, m = blockIdx.y;
    const int tid = threadIdx.x;
    const int e0 = tile * 128;

    __shared__ __align__(16) float xs[128][3];
    __shared__ __align__(16) float W1s[3][HID_DIM];
    __shared__ __align__(16) float b1s[HID_DIM];

    const float* W1 = m ? Wa1 : Wp1;
    const float* b1 = m ? ba1 : bp1;
    for (int i = tid; i < 3 * HID_DIM; i += 256) (&W1s[0][0])[i] = W1[i];
    if (tid < HID_DIM) b1s[tid] = b1[tid];
    if (tid < 128) {
        int e = e0 + tid;
        if (e < ne) {
            xs[tid][0] = x[e * 3 + 0];
            xs[tid][1] = x[e * 3 + 1];
            xs[tid][2] = x[e * 3 + 2];
        } else {
            xs[tid][0] = 0.f; xs[tid][1] = 0.f; xs[tid][2] = 0.f;
        }
    }
    __syncthreads();

    unsigned char* dst = g_Hprep + ((size_t)tile * 2 + m) * BTILE;
    for (int i = tid; i < 8192; i += 256) {
        int el = i >> 6, k = (i & 63) * 2;
        float x0 = xs[el][0], x1 = xs[el][1], x2 = xs[el][2];
        float h0 = b1s[k]     + x0 * W1s[0][k]     + x1 * W1s[1][k]     + x2 * W1s[2][k];
        float h1 = b1s[k + 1] + x0 * W1s[0][k + 1] + x1 * W1s[1][k + 1] + x2 * W1s[2][k + 1];
        h0 = fmaxf(h0, 0.f); h1 = fmaxf(h1, 0.f);
        __half2 v = __floats2half2_rn(h0, h1);
        *(uint32_t*)(dst + el * LDB + k * 2) = *(uint32_t*)&v;
    }
}

// ---------------------------------------------------------------------------
// Bucket electrons (deterministic, index order), 4 per thread per round.
// Bucket b holds electrons with k=floor(z) in [32b-5, 32b+31].
// ---------------------------------------------------------------------------
__global__ void bucket_kernel(const float* __restrict__ zpos, int ne)
{
    const int b = blockIdx.x;
    const int tid = threadIdx.x;
    const float lob = (float)(b * BWID - 5);
    const float hib = (float)(b * BWID + BWID);

    __shared__ int wsum[4][8];
    __shared__ int base0;
    if (tid == 0) base0 = 0;
    __syncthreads();

    const int lane = tid & 31, w = tid >> 5;
    for (int cb = 0; cb < ne; cb += 1024) {
        float z[4]; bool kp[4]; unsigned bm[4];
#pragma unroll
        for (int q = 0; q < 4; q++) {
            int e = cb + q * 256 + tid;
            kp[q] = false; z[q] = 0.f;
            if (e < ne) { z[q] = zpos[e]; kp[q] = (z[q] >= lob) && (z[q] < hib); }
        }
#pragma unroll
        for (int q = 0; q < 4; q++) bm[q] = __ballot_sync(0xffffffffu, kp[q]);
        if (lane == 0)
#pragma unroll
            for (int q = 0; q < 4; q++) wsum[q][w] = __popc(bm[q]);
        __syncthreads();
        if (tid == 0) {
            int run = base0;
#pragma unroll
            for (int q = 0; q < 4; q++)
#pragma unroll
                for (int ww = 0; ww < 8; ww++) {
                    int t = wsum[q][ww]; wsum[q][ww] = run; run += t;
                }
            base0 = run;
        }
        __syncthreads();
#pragma unroll
        for (int q = 0; q < 4; q++) {
            if (kp[q]) {
                int p = wsum[q][w] + __popc(bm[q] & ((1u << lane) - 1u));
                if (p < BCAP) {
                    g_bidx[b * BCAP + p] = cb + q * 256 + tid;
                    g_bz[b * BCAP + p] = z[q];
                }
            }
        }
        __syncthreads();
    }
    if (tid == 0) g_bcnt[b] = (base0 < BCAP) ? base0 : BCAP;
}

// ---------------------------------------------------------------------------
// MLP via mma.sync fp16, cp.async double-buffered A tiles.
// Grid (NSTILE=8, EGRP=18), 512 threads / 16 warps = 4(M32) x 4(N32).
// smem: A[2][2 tiles] + B[2 tiles] = 6*BTILE.
// ---------------------------------------------------------------------------
__global__ __launch_bounds__(512, 1)
void mlp_mma_kernel(const float* __restrict__ maskv,
                    const float* __restrict__ bp2, const float* __restrict__ ba2,
                    int ne)
{
    extern __shared__ __align__(16) unsigned char dyn[];
    __shared__ __align__(16) float bb[2][128];

    const int tid = threadIdx.x;
    const int wid = tid >> 5, lane = tid & 31;
    const int wm = wid >> 2;          // 0..3 over electrons (32 each)
    const int wn = wid & 3;           // 0..3 over sensors (32 each)
    const int stile = blockIdx.x, gy = blockIdx.y;
    const int s0 = stile * 128;
    const int ntiles = (ne + 127) / 128;

    // layout: A buffers [2][2*BTILE], then B [2*BTILE]
    const uint32_t dynS = smem_u32(dyn);
    const uint32_t AbS[2] = { dynS, dynS + 2 * BTILE };
    unsigned char* Bt = dyn + 4 * BTILE;

    if (tid < 128) {
        bb[0][tid] = bp2[s0 + tid];
        bb[1][tid] = ba2[s0 + tid];
    }
    {
        const uint4* src = (const uint4*)(g_Bprep + (size_t)stile * 2 * BTILE);
        uint4* d4 = (uint4*)Bt;
        for (int i = tid; i < (int)(2 * BTILE / 16); i += 512) d4[i] = src[i];
    }

    // prefetch first A tile pair into buffer 0
    if (gy < ntiles) {
        const unsigned char* asrc = g_Hprep + (size_t)gy * 2 * BTILE;
        for (int i = tid; i < 4352; i += 512)
            cp_async16(AbS[0] + (uint32_t)i * 16, asrc + (size_t)i * 16);
    }
    CP_COMMIT();
    __syncthreads();     // B tiles + bb visible

    const uint32_t BtS = smem_u32(Bt);
    const uint32_t lmOff = (uint32_t)(lane & 15) * LDB + (uint32_t)(lane >> 4) * 16;

    int buf = 0;
    for (int et = gy; et < ntiles; et += EGRP) {
        const int e0 = et * 128;

        CP_WAIT0();
        __syncthreads();   // prefetch landed; all warps done with other buffer

        // issue prefetch of next e-tile into the other buffer
        {
            int etn = et + EGRP;
            if (etn < ntiles) {
                const unsigned char* asrc = g_Hprep + (size_t)etn * 2 * BTILE;
                uint32_t dst = AbS[buf ^ 1];
                for (int i = tid; i < 4352; i += 512)
                    cp_async16(dst + (uint32_t)i * 16, asrc + (size_t)i * 16);
            }
            CP_COMMIT();
        }

        const uint32_t ApS = AbS[buf];
        const uint32_t AaS = AbS[buf] + BTILE;

        float accP[2][4][4], accA[2][4][4];
#pragma unroll
        for (int mc = 0; mc < 2; mc++)
#pragma unroll
            for (int nc = 0; nc < 4; nc++)
#pragma unroll
                for (int j = 0; j < 4; j++) { accP[mc][nc][j] = 0.f; accA[mc][nc][j] = 0.f; }

        const uint32_t aRow0 = (uint32_t)(wm * 32) * LDB + lmOff;
        const uint32_t aRow1 = (uint32_t)(wm * 32 + 16) * LDB + lmOff;
        const uint32_t bCol0 = (uint32_t)(wn * 32) * 2 + lmOff;
        const uint32_t bCol1 = (uint32_t)(wn * 32 + 16) * 2 + lmOff;

#pragma unroll
        for (int ks = 0; ks < 8; ks++) {
            const uint32_t kb = (uint32_t)ks * 32;
            const uint32_t krow = (uint32_t)ks * 16 * LDB;
            uint32_t a0[4], a1[4], b0[4], b1[4];

            // ======== prob MLP ========
            ldsm_x4(a0, ApS + aRow0 + kb);
            ldsm_x4(a1, ApS + aRow1 + kb);
            ldsm_x4_t(b0, BtS + krow + bCol0);
            ldsm_x4_t(b1, BtS + krow + bCol1);
            mma_f16(accP[0][0], a0, &b0[0]); mma_f16(accP[0][1], a0, &b0[2]);
            mma_f16(accP[0][2], a0, &b1[0]); mma_f16(accP[0][3], a0, &b1[2]);
            mma_f16(accP[1][0], a1, &b0[0]); mma_f16(accP[1][1], a1, &b0[2]);
            mma_f16(accP[1][2], a1, &b1[0]); mma_f16(accP[1][3], a1, &b1[2]);

            // ======== amp MLP ========
            ldsm_x4(a0, AaS + aRow0 + kb);
            ldsm_x4(a1, AaS + aRow1 + kb);
            ldsm_x4_t(b0, BtS + BTILE + krow + bCol0);
            ldsm_x4_t(b1, BtS + BTILE + krow + bCol1);
            mma_f16(accA[0][0], a0, &b0[0]); mma_f16(accA[0][1], a0, &b0[2]);
            mma_f16(accA[0][2], a0, &b1[0]); mma_f16(accA[0][3], a0, &b1[2]);
            mma_f16(accA[1][0], a1, &b0[0]); mma_f16(accA[1][1], a1, &b0[2]);
            mma_f16(accA[1][2], a1, &b1[0]); mma_f16(accA[1][3], a1, &b1[2]);
        }

        // epilogue: fused bias+sigmoid+amp+mask, fp16 stores
#pragma unroll
        for (int mc = 0; mc < 2; mc++) {
            int ra = e0 + wm * 32 + mc * 16 + (lane >> 2);
            int rb = ra + 8;
            float mka = (ra < ne) ? maskv[ra] : 0.f;
            float mkb = (rb < ne) ? maskv[rb] : 0.f;
#pragma unroll
            for (int nc = 0; nc < 4; nc++) {
                int col = wn * 32 + nc * 8 + (lane & 3) * 2;
                float bp0 = bb[0][col], bp1v = bb[0][col + 1];
                float ba0 = bb[1][col], ba1v = bb[1][col + 1];
                float p0 = accP[mc][nc][0] + bp0, p1 = accP[mc][nc][1] + bp1v;
                float p2 = accP[mc][nc][2] + bp0, p3 = accP[mc][nc][3] + bp1v;
                float A0 = accA[mc][nc][0] + ba0, A1 = accA[mc][nc][1] + ba1v;
                float A2 = accA[mc][nc][2] + ba0, A3 = accA[mc][nc][3] + ba1v;
                float o0 = A0 * mka * (1.0f / (1.0f + expf(-p0)));
                float o1 = A1 * mka * (1.0f / (1.0f + expf(-p1)));
                float o2 = A2 * mkb * (1.0f / (1.0f + expf(-p2)));
                float o3 = A3 * mkb * (1.0f / (1.0f + expf(-p3)));
                if (ra < ne) *(__half2*)&g_resph[(size_t)ra * S_DIM + s0 + col] =
                    __floats2half2_rn(o0, o1);
                if (rb < ne) *(__half2*)&g_resph[(size_t)rb * S_DIM + s0 + col] =
                    __floats2half2_rn(o2, o3);
            }
        }

        buf ^= 1;
    }
}

// ---------------------------------------------------------------------------
// Stage A as dense GEMM per bucket: D[32, s] = W[32, e] @ resp[e, s], fp16.
// grid (8 s-tiles of 128, 33 buckets), 256 threads / 8 warps = 2(M16) x 4(N32).
// ---------------------------------------------------------------------------
__global__ __launch_bounds__(256)
void stageA_kernel()
{
    const int s0 = blockIdx.x * 128;
    const int b = blockIdx.y;
    const int tid = threadIdx.x;
    const int wid = tid >> 5, lane = tid & 31;
    const int wm = wid >> 2;          // 0..1 (16 tap rows each)
    const int wn = wid & 3;           // 0..3 (32 sensors each)

    __shared__ __align__(16) unsigned char Wt[32 * LDB];      // [32 c][136 e] fp16
    __shared__ __align__(16) unsigned char Rt[128 * LDB];     // [128 e][136 s] fp16
    __shared__ int ech[128];

    const int cnt = g_bcnt[b];
    const int c0 = b * BWID;

    float acc[4][4];
#pragma unroll
    for (int nt = 0; nt < 4; nt++)
#pragma unroll
        for (int j = 0; j < 4; j++) acc[nt][j] = 0.f;

    const uint32_t WtS = smem_u32(Wt), RtS = smem_u32(Rt);
    const uint32_t lmOff = (uint32_t)(lane & 15) * LDB + (uint32_t)(lane >> 4) * 16;

    for (int base = 0; base < cnt; base += 128) {
        int n = cnt - base; if (n > 128) n = 128;

        float z = 0.f; int eidx = 0;
        if (tid < n) {
            z = g_bz[b * BCAP + base + tid];
            eidx = g_bidx[b * BCAP + base + tid];
        }

        for (int i = tid; i < 32 * LDB / 4; i += 256) ((uint32_t*)Wt)[i] = 0u;
        if (tid < n) ech[tid] = eidx;
        __syncthreads();

        if (tid < n) {
            float kf = floorf(z);
            float f = z - kf;
            int kl = (int)kf - c0;                 // in [-5, 31]
            float t0 = f + 2.f, t1 = f + 1.f, t2 = f, t3 = f - 1.f,
                  t4 = f - 2.f, t5 = f - 3.f;
            float w[6];
            w[0] = t1 * t2 * t3 * t4 * t5 * (-1.f / 120.f);
            w[1] = t0 * t2 * t3 * t4 * t5 * ( 1.f /  24.f);
            w[2] = t0 * t1 * t3 * t4 * t5 * (-1.f /  12.f);
            w[3] = t0 * t1 * t2 * t4 * t5 * ( 1.f /  12.f);
            w[4] = t0 * t1 * t2 * t3 * t5 * (-1.f /  24.f);
            w[5] = t0 * t1 * t2 * t3 * t4 * ( 1.f / 120.f);
#pragma unroll
            for (int j = 0; j < 6; j++) {
                int c = kl + j;
                if (c >= 0 && c < 32)
                    *(__half*)(Wt + c * LDB + tid * 2) = __float2half_rn(w[j]);
            }
        }

        for (int i = tid; i < n * 16; i += 256) {
            int e = i >> 4, q = i & 15;
            ((uint4*)(Rt + e * LDB))[q] =
                ((const uint4*)&g_resph[(size_t)ech[e] * S_DIM + s0])[q];
        }
        __syncthreads();

#pragma unroll
        for (int ks = 0; ks < 8; ks++) {
            uint32_t a0[4], bf[2][4];
            ldsm_x4(a0, WtS + (uint32_t)(wm * 16) * LDB + (uint32_t)ks * 32 + lmOff);
#pragma unroll
            for (int nb = 0; nb < 2; nb++)
                ldsm_x4_t(bf[nb], RtS + (uint32_t)(ks * 16) * LDB +
                                  (uint32_t)(wn * 32 + nb * 16) * 2 + lmOff);
#pragma unroll
            for (int nb = 0; nb < 2; nb++) {
                mma_f16(acc[2 * nb],     a0, &bf[nb][0]);
                mma_f16(acc[2 * nb + 1], a0, &bf[nb][2]);
            }
        }
        __syncthreads();
    }

    const int r0 = c0 + wm * 16 + (lane >> 2);
    const int colb = s0 + wn * 32 + (lane & 3) * 2;
#pragma unroll
    for (int nt = 0; nt < 4; nt++) {
        int col = colb + nt * 8;
        *(float2*)&g_D[(size_t)r0 * S_DIM + col] = make_float2(acc[nt][0], acc[nt][1]);
        *(float2*)&g_D[(size_t)(r0 + 8) * S_DIM + col] = make_float2(acc[nt][2], acc[nt][3]);
    }
}

// ---------------------------------------------------------------------------
// Banded 1-D convolution out[s,t] = sum_tau D[tau+2,s] * G(t-tau).
// ---------------------------------------------------------------------------
__global__ __launch_bounds__(256)
void conv_kernel(const float* __restrict__ sig, float* __restrict__ out)
{
    __shared__ float Db[2 * RMAX + 33][64];
    __shared__ float Gs[2 * RMAX + 1];

    const int s0 = blockIdx.x * 64;
    const int t0 = blockIdx.y * 32;
    const int tid = threadIdx.x;

    const float sigma  = sig[0];
    const float inv2s2 = 1.0f / (2.0f * sigma * sigma);
    const float coef   = 0.3989422804f / sqrtf(sigma * sigma);
    int R = (int)ceilf(sigma * 7.746f);
    if (R < 1) R = 1;
    if (R > RMAX) R = RMAX;
    const int nG = 2 * R + 1;
    const int rows = 2 * R + 33;
    const int rlo = t0 - R + 2;

    for (int i = tid; i < nG; i += 256) {
        float d = (float)(i - R);
        Gs[i] = coef * expf(-d * d * inv2s2);
    }
    for (int idx = tid; idx < rows * 64; idx += 256) {
        int ri = idx >> 6, s2 = idx & 63;
        int c = rlo + ri;
        Db[ri][s2] = (c >= 0 && c < T_DIM + 4) ?
            g_D[(size_t)c * S_DIM + s0 + s2] : 0.f;
    }
    __syncthreads();

    const int sl = tid & 31;
    const int tq = tid >> 5;
    const int tb = tq * 4;

    float acc0[4] = {0.f, 0.f, 0.f, 0.f};
    float acc1[4] = {0.f, 0.f, 0.f, 0.f};

    for (int ri = 0; ri < rows; ri++) {
        float v0 = Db[ri][sl];
        float v1 = Db[ri][sl + 32];
#pragma unroll
        for (int k = 0; k < 4; k++) {
            int gi = ri - tb - k;
            if (gi >= 0 && gi < nG) {
                float w = Gs[gi];
                acc0[k] = fmaf(v0, w, acc0[k]);
                acc1[k] = fmaf(v1, w, acc1[k]);
            }
        }
    }

    *(float4*)&out[(size_t)(s0 + sl) * T_DIM + t0 + tb] =
        make_float4(acc0[0], acc0[1], acc0[2], acc0[3]);
    *(float4*)&out[(size_t)(s0 + sl + 32) * T_DIM + t0 + tb] =
        make_float4(acc1[0], acc1[1], acc1[2], acc1[3]);
}

// ---------------------------------------------------------------------------
extern "C" void kernel_launch(void* const* d_in, const int* in_sizes, int n_in,
                              void* d_out, int out_size)
{
    const float* x    = (const float*)d_in[0];
    const float* zpos = (const float*)d_in[1];
    const float* mask = (const float*)d_in[2];
    const float* Wp1  = (const float*)d_in[3];
    const float* bp1  = (const float*)d_in[4];
    const float* Wp2  = (const float*)d_in[5];
    const float* bp2  = (const float*)d_in[6];
    const float* Wa1  = (const float*)d_in[7];
    const float* ba1  = (const float*)d_in[8];
    const float* Wa2  = (const float*)d_in[9];
    const float* ba2  = (const float*)d_in[10];
    const float* sig  = (const float*)d_in[11];

    int ne = in_sizes[1];
    if (ne > NE_MAX) ne = NE_MAX;
    int ntiles = (ne + 127) / 128;

    const int dyn_bytes = 6 * BTILE;   // 2x(2 A tiles) + 2 B tiles = 208896 B
    cudaFuncSetAttribute(mlp_mma_kernel,
                         cudaFuncAttributeMaxDynamicSharedMemorySize, dyn_bytes);

    prep_kernel<<<dim3(NSTILE, 2), 256>>>(Wp2, Wa2);
    prepH_kernel<<<dim3(ntiles, 2), 256>>>(x, Wp1, bp1, Wa1, ba1, ne);
    bucket_kernel<<<NBUCKET, 256>>>(zpos, ne);

    mlp_mma_kernel<<<dim3(NSTILE, EGRP), 512, dyn_bytes>>>(mask, bp2, ba2, ne);

    stageA_kernel<<<dim3(S_DIM / 128, NBUCKET), 256>>>();

    conv_kernel<<<dim3(S_DIM / 64, T_DIM / 32), 256>>>(sig, (float*)d_out);
}

// round 17
// speedup vs baseline: 2.4591x; 1.2408x over previous
#include <cuda_runtime.h>
#include <cuda_fp16.h>
#include <math.h>
#include <stdint.h>

#define S_DIM 1024
#define T_DIM 1024
#define HID_DIM 128
#define NE_MAX 32000
#define NETILES 250          // ceil(NE_MAX/128)
#define NBUCKET 33
#define BWID 32              // bucket width in tap columns
#define BCAP 2048
#define RMAX 72
#define NSTILE 8
#define EGRP 18
#define BTILE 34816u         // one [128][136] fp16 tile in bytes
#define LDT 136              // padded row length (fp16 elems)
#define LDB (LDT * 2)        // row bytes = 272
#define WTB (32 * LDB)       // W tile bytes = 8704

// ---------------- scratch (__device__ globals) ----------------
__device__ __align__(16) __half g_resph[(size_t)NE_MAX * S_DIM];            // [e][s]
__device__ __align__(16) float g_D[(size_t)NBUCKET * BWID * S_DIM];         // [c][s]
__device__ int   g_bcnt[NBUCKET];
__device__ int   g_bidx[NBUCKET * BCAP];
__device__ float g_bz[NBUCKET * BCAP];
// fp16 weight tiles [stile][p,a][128k][136n]
__device__ __align__(16) unsigned char g_Bprep[(size_t)NSTILE * 2 * BTILE];
// precomputed hidden activations [etile][p,a][128el][LDT k]
__device__ __align__(16) unsigned char g_Hprep[(size_t)NETILES * 2 * BTILE];

// ---------------- helpers ----------------
__device__ __forceinline__ uint32_t smem_u32(const void* p) {
    uint32_t a;
    asm("{ .reg .u64 t; cvta.to.shared.u64 t, %1; cvt.u32.u64 %0, t; }"
        : "=r"(a) : "l"(p));
    return a;
}
__device__ __forceinline__ void ldsm_x4(uint32_t* r, uint32_t addr) {
    asm volatile("ldmatrix.sync.aligned.m8n8.x4.shared.b16 {%0,%1,%2,%3}, [%4];"
                 : "=r"(r[0]), "=r"(r[1]), "=r"(r[2]), "=r"(r[3]) : "r"(addr));
}
__device__ __forceinline__ void ldsm_x4_t(uint32_t* r, uint32_t addr) {
    asm volatile("ldmatrix.sync.aligned.m8n8.x4.trans.shared.b16 {%0,%1,%2,%3}, [%4];"
                 : "=r"(r[0]), "=r"(r[1]), "=r"(r[2]), "=r"(r[3]) : "r"(addr));
}
__device__ __forceinline__ void mma_f16(float* c, const uint32_t* a, const uint32_t* b) {
    asm volatile("mma.sync.aligned.m16n8k16.row.col.f32.f16.f16.f32 "
                 "{%0,%1,%2,%3}, {%4,%5,%6,%7}, {%8,%9}, {%0,%1,%2,%3};"
                 : "+f"(c[0]), "+f"(c[1]), "+f"(c[2]), "+f"(c[3])
                 : "r"(a[0]), "r"(a[1]), "r"(a[2]), "r"(a[3]), "r"(b[0]), "r"(b[1]));
}
__device__ __forceinline__ void cp_async16(uint32_t saddr, const void* gptr) {
    asm volatile("cp.async.cg.shared.global [%0], [%1], 16;"
                 :: "r"(saddr), "l"(gptr));
}
#define CP_COMMIT() asm volatile("cp.async.commit_group;" ::: "memory")
#define CP_WAIT0()  asm volatile("cp.async.wait_group 0;" ::: "memory")

// ---------------------------------------------------------------------------
// Prep: W2 as fp16 tiles [k][136] row-major. grid (NSTILE, 2): y=0 prob, 1 amp.
// ---------------------------------------------------------------------------
__global__ void prep_kernel(const float* __restrict__ Wp2, const float* __restrict__ Wa2)
{
    const int stile = blockIdx.x, m = blockIdx.y;
    const int s0 = stile * 128;
    const float* W2 = m ? Wa2 : Wp2;
    __half* dst = (__half*)(g_Bprep + ((size_t)stile * 2 + m) * BTILE);
    for (int idx = threadIdx.x; idx < 128 * 128; idx += 256) {
        int k = idx >> 7, n = idx & 127;
        dst[k * LDT + n] = __float2half_rn(W2[(size_t)k * S_DIM + s0 + n]);
    }
}

// ---------------------------------------------------------------------------
// PrepH: hidden layer H = relu(x@W1+b1) as fp16 A-tiles [el][k], stride LDT.
// ---------------------------------------------------------------------------
__global__ void prepH_kernel(const float* __restrict__ x,
                             const float* __restrict__ Wp1, const float* __restrict__ bp1,
                             const float* __restrict__ Wa1, const float* __restrict__ ba1,
                             int ne)
{
    const int tile = blockIdx.x, m = blockIdx.y;
    const int tid = threadIdx.x;
    const int e0 = tile * 128;

    __shared__ __align__(16) float xs[128][3];
    __shared__ __align__(16) float W1s[3][HID_DIM];
    __shared__ __align__(16) float b1s[HID_DIM];

    const float* W1 = m ? Wa1 : Wp1;
    const float* b1 = m ? ba1 : bp1;
    for (int i = tid; i < 3 * HID_DIM; i += 256) (&W1s[0][0])[i] = W1[i];
    if (tid < HID_DIM) b1s[tid] = b1[tid];
    if (tid < 128) {
        int e = e0 + tid;
        if (e < ne) {
            xs[tid][0] = x[e * 3 + 0];
            xs[tid][1] = x[e * 3 + 1];
            xs[tid][2] = x[e * 3 + 2];
        } else {
            xs[tid][0] = 0.f; xs[tid][1] = 0.f; xs[tid][2] = 0.f;
        }
    }
    __syncthreads();

    unsigned char* dst = g_Hprep + ((size_t)tile * 2 + m) * BTILE;
    for (int i = tid; i < 8192; i += 256) {
        int el = i >> 6, k = (i & 63) * 2;
        float x0 = xs[el][0], x1 = xs[el][1], x2 = xs[el][2];
        float h0 = b1s[k]     + x0 * W1s[0][k]     + x1 * W1s[1][k]     + x2 * W1s[2][k];
        float h1 = b1s[k + 1] + x0 * W1s[0][k + 1] + x1 * W1s[1][k + 1] + x2 * W1s[2][k + 1];
        h0 = fmaxf(h0, 0.f); h1 = fmaxf(h1, 0.f);
        __half2 v = __floats2half2_rn(h0, h1);
        *(uint32_t*)(dst + el * LDB + k * 2) = *(uint32_t*)&v;
    }
}

// ---------------------------------------------------------------------------
// Bucket electrons (deterministic, index order), 4 per thread per round.
// Bucket b holds electrons with k=floor(z) in [32b-5, 32b+31].
// ---------------------------------------------------------------------------
__global__ void bucket_kernel(const float* __restrict__ zpos, int ne)
{
    const int b = blockIdx.x;
    const int tid = threadIdx.x;
    const float lob = (float)(b * BWID - 5);
    const float hib = (float)(b * BWID + BWID);

    __shared__ int wsum[4][8];
    __shared__ int base0;
    if (tid == 0) base0 = 0;
    __syncthreads();

    const int lane = tid & 31, w = tid >> 5;
    for (int cb = 0; cb < ne; cb += 1024) {
        float z[4]; bool kp[4]; unsigned bm[4];
#pragma unroll
        for (int q = 0; q < 4; q++) {
            int e = cb + q * 256 + tid;
            kp[q] = false; z[q] = 0.f;
            if (e < ne) { z[q] = zpos[e]; kp[q] = (z[q] >= lob) && (z[q] < hib); }
        }
#pragma unroll
        for (int q = 0; q < 4; q++) bm[q] = __ballot_sync(0xffffffffu, kp[q]);
        if (lane == 0)
#pragma unroll
            for (int q = 0; q < 4; q++) wsum[q][w] = __popc(bm[q]);
        __syncthreads();
        if (tid == 0) {
            int run = base0;
#pragma unroll
            for (int q = 0; q < 4; q++)
#pragma unroll
                for (int ww = 0; ww < 8; ww++) {
                    int t = wsum[q][ww]; wsum[q][ww] = run; run += t;
                }
            base0 = run;
        }
        __syncthreads();
#pragma unroll
        for (int q = 0; q < 4; q++) {
            if (kp[q]) {
                int p = wsum[q][w] + __popc(bm[q] & ((1u << lane) - 1u));
                if (p < BCAP) {
                    g_bidx[b * BCAP + p] = cb + q * 256 + tid;
                    g_bz[b * BCAP + p] = z[q];
                }
            }
        }
        __syncthreads();
    }
    if (tid == 0) g_bcnt[b] = (base0 < BCAP) ? base0 : BCAP;
}

// ---------------------------------------------------------------------------
// MLP via mma.sync fp16, cp.async double-buffered A tiles.
// Grid (NSTILE=8, EGRP=18), 512 threads / 16 warps = 4(M32) x 4(N32).
// ---------------------------------------------------------------------------
__global__ __launch_bounds__(512, 1)
void mlp_mma_kernel(const float* __restrict__ maskv,
                    const float* __restrict__ bp2, const float* __restrict__ ba2,
                    int ne)
{
    extern __shared__ __align__(16) unsigned char dyn[];
    __shared__ __align__(16) float bb[2][128];

    const int tid = threadIdx.x;
    const int wid = tid >> 5, lane = tid & 31;
    const int wm = wid >> 2;          // 0..3 over electrons (32 each)
    const int wn = wid & 3;           // 0..3 over sensors (32 each)
    const int stile = blockIdx.x, gy = blockIdx.y;
    const int s0 = stile * 128;
    const int ntiles = (ne + 127) / 128;

    const uint32_t dynS = smem_u32(dyn);
    const uint32_t AbS[2] = { dynS, dynS + 2 * BTILE };
    unsigned char* Bt = dyn + 4 * BTILE;

    if (tid < 128) {
        bb[0][tid] = bp2[s0 + tid];
        bb[1][tid] = ba2[s0 + tid];
    }
    {
        const uint4* src = (const uint4*)(g_Bprep + (size_t)stile * 2 * BTILE);
        uint4* d4 = (uint4*)Bt;
        for (int i = tid; i < (int)(2 * BTILE / 16); i += 512) d4[i] = src[i];
    }

    if (gy < ntiles) {
        const unsigned char* asrc = g_Hprep + (size_t)gy * 2 * BTILE;
        for (int i = tid; i < 4352; i += 512)
            cp_async16(AbS[0] + (uint32_t)i * 16, asrc + (size_t)i * 16);
    }
    CP_COMMIT();
    __syncthreads();

    const uint32_t BtS = smem_u32(Bt);
    const uint32_t lmOff = (uint32_t)(lane & 15) * LDB + (uint32_t)(lane >> 4) * 16;

    int buf = 0;
    for (int et = gy; et < ntiles; et += EGRP) {
        const int e0 = et * 128;

        CP_WAIT0();
        __syncthreads();

        {
            int etn = et + EGRP;
            if (etn < ntiles) {
                const unsigned char* asrc = g_Hprep + (size_t)etn * 2 * BTILE;
                uint32_t dst = AbS[buf ^ 1];
                for (int i = tid; i < 4352; i += 512)
                    cp_async16(dst + (uint32_t)i * 16, asrc + (size_t)i * 16);
            }
            CP_COMMIT();
        }

        const uint32_t ApS = AbS[buf];
        const uint32_t AaS = AbS[buf] + BTILE;

        float accP[2][4][4], accA[2][4][4];
#pragma unroll
        for (int mc = 0; mc < 2; mc++)
#pragma unroll
            for (int nc = 0; nc < 4; nc++)
#pragma unroll
                for (int j = 0; j < 4; j++) { accP[mc][nc][j] = 0.f; accA[mc][nc][j] = 0.f; }

        const uint32_t aRow0 = (uint32_t)(wm * 32) * LDB + lmOff;
        const uint32_t aRow1 = (uint32_t)(wm * 32 + 16) * LDB + lmOff;
        const uint32_t bCol0 = (uint32_t)(wn * 32) * 2 + lmOff;
        const uint32_t bCol1 = (uint32_t)(wn * 32 + 16) * 2 + lmOff;

#pragma unroll
        for (int ks = 0; ks < 8; ks++) {
            const uint32_t kb = (uint32_t)ks * 32;
            const uint32_t krow = (uint32_t)ks * 16 * LDB;
            uint32_t a0[4], a1[4], b0[4], b1[4];

            ldsm_x4(a0, ApS + aRow0 + kb);
            ldsm_x4(a1, ApS + aRow1 + kb);
            ldsm_x4_t(b0, BtS + krow + bCol0);
            ldsm_x4_t(b1, BtS + krow + bCol1);
            mma_f16(accP[0][0], a0, &b0[0]); mma_f16(accP[0][1], a0, &b0[2]);
            mma_f16(accP[0][2], a0, &b1[0]); mma_f16(accP[0][3], a0, &b1[2]);
            mma_f16(accP[1][0], a1, &b0[0]); mma_f16(accP[1][1], a1, &b0[2]);
            mma_f16(accP[1][2], a1, &b1[0]); mma_f16(accP[1][3], a1, &b1[2]);

            ldsm_x4(a0, AaS + aRow0 + kb);
            ldsm_x4(a1, AaS + aRow1 + kb);
            ldsm_x4_t(b0, BtS + BTILE + krow + bCol0);
            ldsm_x4_t(b1, BtS + BTILE + krow + bCol1);
            mma_f16(accA[0][0], a0, &b0[0]); mma_f16(accA[0][1], a0, &b0[2]);
            mma_f16(accA[0][2], a0, &b1[0]); mma_f16(accA[0][3], a0, &b1[2]);
            mma_f16(accA[1][0], a1, &b0[0]); mma_f16(accA[1][1], a1, &b0[2]);
            mma_f16(accA[1][2], a1, &b1[0]); mma_f16(accA[1][3], a1, &b1[2]);
        }

        // epilogue: fused bias + fast sigmoid + amp + mask, fp16 stores
#pragma unroll
        for (int mc = 0; mc < 2; mc++) {
            int ra = e0 + wm * 32 + mc * 16 + (lane >> 2);
            int rb = ra + 8;
            float mka = (ra < ne) ? maskv[ra] : 0.f;
            float mkb = (rb < ne) ? maskv[rb] : 0.f;
#pragma unroll
            for (int nc = 0; nc < 4; nc++) {
                int col = wn * 32 + nc * 8 + (lane & 3) * 2;
                float bp0 = bb[0][col], bp1v = bb[0][col + 1];
                float ba0 = bb[1][col], ba1v = bb[1][col + 1];
                float p0 = accP[mc][nc][0] + bp0, p1 = accP[mc][nc][1] + bp1v;
                float p2 = accP[mc][nc][2] + bp0, p3 = accP[mc][nc][3] + bp1v;
                float A0 = accA[mc][nc][0] + ba0, A1 = accA[mc][nc][1] + ba1v;
                float A2 = accA[mc][nc][2] + ba0, A3 = accA[mc][nc][3] + ba1v;
                float o0 = __fdividef(A0 * mka, 1.0f + __expf(-p0));
                float o1 = __fdividef(A1 * mka, 1.0f + __expf(-p1));
                float o2 = __fdividef(A2 * mkb, 1.0f + __expf(-p2));
                float o3 = __fdividef(A3 * mkb, 1.0f + __expf(-p3));
                if (ra < ne) *(__half2*)&g_resph[(size_t)ra * S_DIM + s0 + col] =
                    __floats2half2_rn(o0, o1);
                if (rb < ne) *(__half2*)&g_resph[(size_t)rb * S_DIM + s0 + col] =
                    __floats2half2_rn(o2, o3);
            }
        }

        buf ^= 1;
    }
}

// ---------------------------------------------------------------------------
// Stage A as dense GEMM per bucket, cp.async double-buffered.
// D[32, s] = W[32, e] @ resp[e, s], fp16. grid (8 s-tiles, 33 buckets),
// 256 threads / 8 warps = 2(M16) x 4(N32).
// Thread t (<128) owns W column t: writes all 32 rows (taps or 0) — no race.
// ---------------------------------------------------------------------------
__global__ __launch_bounds__(256)
void stageA_kernel()
{
    extern __shared__ __align__(16) unsigned char sdyn[];
    const int s0 = blockIdx.x * 128;
    const int b = blockIdx.y;
    const int tid = threadIdx.x;
    const int wid = tid >> 5, lane = tid & 31;
    const int wm = wid >> 2;          // 0..1 (16 tap rows each)
    const int wn = wid & 3;           // 0..3 (32 sensors each)

    const uint32_t sdynS = smem_u32(sdyn);
    const uint32_t WtS[2] = { sdynS, sdynS + WTB };
    const uint32_t RtS[2] = { sdynS + 2 * WTB, sdynS + 2 * WTB + 128 * LDB };

    const int cnt = g_bcnt[b];
    const int c0 = b * BWID;
    const int nchunks = (cnt + 127) / 128;

    float acc[4][4];
#pragma unroll
    for (int nt = 0; nt < 4; nt++)
#pragma unroll
        for (int j = 0; j < 4; j++) acc[nt][j] = 0.f;

    const uint32_t lmOff = (uint32_t)(lane & 15) * LDB + (uint32_t)(lane >> 4) * 16;

    // stage chunk (base) into buffer bb: W columns + Rt rows (cp.async)
    auto stage = [&](int base, int bb) {
        int n = cnt - base; if (n > 128) n = 128;
        if (tid < 128) {
            float w[6];
            int kl = 1000;
            if (tid < n) {
                float z = g_bz[b * BCAP + base + tid];
                float kf = floorf(z);
                float f = z - kf;
                kl = (int)kf - c0;                 // in [-5, 31]
                float t0 = f + 2.f, t1 = f + 1.f, t2 = f, t3 = f - 1.f,
                      t4 = f - 2.f, t5 = f - 3.f;
                w[0] = t1 * t2 * t3 * t4 * t5 * (-1.f / 120.f);
                w[1] = t0 * t2 * t3 * t4 * t5 * ( 1.f /  24.f);
                w[2] = t0 * t1 * t3 * t4 * t5 * (-1.f /  12.f);
                w[3] = t0 * t1 * t2 * t4 * t5 * ( 1.f /  12.f);
                w[4] = t0 * t1 * t2 * t3 * t5 * (-1.f /  24.f);
                w[5] = t0 * t1 * t2 * t3 * t4 * ( 1.f / 120.f);
            }
            uint32_t wcol = WtS[bb] + (uint32_t)tid * 2;
#pragma unroll
            for (int c = 0; c < 32; c++) {
                int j = c - kl;
                float v = (j >= 0 && j < 6) ? w[j] : 0.f;
                __half hv = __float2half_rn(v);
                asm volatile("st.shared.b16 [%0], %1;"
                             :: "r"(wcol + (uint32_t)c * LDB), "h"(*(unsigned short*)&hv));
            }
        }
        for (int i = tid; i < n * 16; i += 256) {
            int e = i >> 4, q = i & 15;
            int ge = g_bidx[b * BCAP + base + e];
            cp_async16(RtS[bb] + (uint32_t)e * LDB + (uint32_t)q * 16,
                       (const unsigned char*)&g_resph[(size_t)ge * S_DIM + s0] + q * 16);
        }
    };

    if (nchunks > 0) stage(0, 0);
    CP_COMMIT();

    int buf = 0;
    for (int ch = 0; ch < nchunks; ch++) {
        CP_WAIT0();
        __syncthreads();     // buffer `buf` ready; all warps done with buf^1

        if (ch + 1 < nchunks) stage((ch + 1) * 128, buf ^ 1);
        CP_COMMIT();

#pragma unroll
        for (int ks = 0; ks < 8; ks++) {
            uint32_t a0[4], bf[2][4];
            ldsm_x4(a0, WtS[buf] + (uint32_t)(wm * 16) * LDB + (uint32_t)ks * 32 + lmOff);
#pragma unroll
            for (int nb = 0; nb < 2; nb++)
                ldsm_x4_t(bf[nb], RtS[buf] + (uint32_t)(ks * 16) * LDB +
                                  (uint32_t)(wn * 32 + nb * 16) * 2 + lmOff);
#pragma unroll
            for (int nb = 0; nb < 2; nb++) {
                mma_f16(acc[2 * nb],     a0, &bf[nb][0]);
                mma_f16(acc[2 * nb + 1], a0, &bf[nb][2]);
            }
        }
        buf ^= 1;
    }

    const int r0 = c0 + wm * 16 + (lane >> 2);
    const int colb = s0 + wn * 32 + (lane & 3) * 2;
#pragma unroll
    for (int nt = 0; nt < 4; nt++) {
        int col = colb + nt * 8;
        *(float2*)&g_D[(size_t)r0 * S_DIM + col] = make_float2(acc[nt][0], acc[nt][1]);
        *(float2*)&g_D[(size_t)(r0 + 8) * S_DIM + col] = make_float2(acc[nt][2], acc[nt][3]);
    }
}

// ---------------------------------------------------------------------------
// Banded 1-D convolution out[s,t] = sum_tau D[tau+2,s] * G(t-tau).
// Loop bounds tightened: only ri in [tb, tb+nG+4) contribute.
// ---------------------------------------------------------------------------
__global__ __launch_bounds__(256)
void conv_kernel(const float* __restrict__ sig, float* __restrict__ out)
{
    __shared__ float Db[2 * RMAX + 33][64];
    __shared__ float Gs[2 * RMAX + 1];

    const int s0 = blockIdx.x * 64;
    const int t0 = blockIdx.y * 32;
    const int tid = threadIdx.x;

    const float sigma  = sig[0];
    const float inv2s2 = 1.0f / (2.0f * sigma * sigma);
    const float coef   = 0.3989422804f / sqrtf(sigma * sigma);
    int R = (int)ceilf(sigma * 7.746f);
    if (R < 1) R = 1;
    if (R > RMAX) R = RMAX;
    const int nG = 2 * R + 1;
    const int rows = 2 * R + 33;
    const int rlo = t0 - R + 2;

    for (int i = tid; i < nG; i += 256) {
        float d = (float)(i - R);
        Gs[i] = coef * expf(-d * d * inv2s2);
    }
    for (int idx = tid; idx < rows * 64; idx += 256) {
        int ri = idx >> 6, s2 = idx & 63;
        int c = rlo + ri;
        Db[ri][s2] = (c >= 0 && c < T_DIM + 4) ?
            g_D[(size_t)c * S_DIM + s0 + s2] : 0.f;
    }
    __syncthreads();

    const int sl = tid & 31;
    const int tq = tid >> 5;
    const int tb = tq * 4;

    float acc0[4] = {0.f, 0.f, 0.f, 0.f};
    float acc1[4] = {0.f, 0.f, 0.f, 0.f};

    int riEnd = tb + nG + 4; if (riEnd > rows) riEnd = rows;
    for (int ri = tb; ri < riEnd; ri++) {
        float v0 = Db[ri][sl];
        float v1 = Db[ri][sl + 32];
#pragma unroll
        for (int k = 0; k < 4; k++) {
            int gi = ri - tb - k;
            if (gi >= 0 && gi < nG) {
                float w = Gs[gi];
                acc0[k] = fmaf(v0, w, acc0[k]);
                acc1[k] = fmaf(v1, w, acc1[k]);
            }
        }
    }

    *(float4*)&out[(size_t)(s0 + sl) * T_DIM + t0 + tb] =
        make_float4(acc0[0], acc0[1], acc0[2], acc0[3]);
    *(float4*)&out[(size_t)(s0 + sl + 32) * T_DIM + t0 + tb] =
        make_float4(acc1[0], acc1[1], acc1[2], acc1[3]);
}

// ---------------------------------------------------------------------------
extern "C" void kernel_launch(void* const* d_in, const int* in_sizes, int n_in,
                              void* d_out, int out_size)
{
    const float* x    = (const float*)d_in[0];
    const float* zpos = (const float*)d_in[1];
    const float* mask = (const float*)d_in[2];
    const float* Wp1  = (const float*)d_in[3];
    const float* bp1  = (const float*)d_in[4];
    const float* Wp2  = (const float*)d_in[5];
    const float* bp2  = (const float*)d_in[6];
    const float* Wa1  = (const float*)d_in[7];
    const float* ba1  = (const float*)d_in[8];
    const float* Wa2  = (const float*)d_in[9];
    const float* ba2  = (const float*)d_in[10];
    const float* sig  = (const float*)d_in[11];

    int ne = in_sizes[1];
    if (ne > NE_MAX) ne = NE_MAX;
    int ntiles = (ne + 127) / 128;

    const int mlp_dyn = 6 * BTILE;                 // 208896 B
    const int sA_dyn = 2 * WTB + 2 * 128 * LDB;    // 87040 B
    cudaFuncSetAttribute(mlp_mma_kernel,
                         cudaFuncAttributeMaxDynamicSharedMemorySize, mlp_dyn);
    cudaFuncSetAttribute(stageA_kernel,
                         cudaFuncAttributeMaxDynamicSharedMemorySize, sA_dyn);

    prep_kernel<<<dim3(NSTILE, 2), 256>>>(Wp2, Wa2);
    prepH_kernel<<<dim3(ntiles, 2), 256>>>(x, Wp1, bp1, Wa1, ba1, ne);
    bucket_kernel<<<NBUCKET, 256>>>(zpos, ne);

    mlp_mma_kernel<<<dim3(NSTILE, EGRP), 512, mlp_dyn>>>(mask, bp2, ba2, ne);

    stageA_kernel<<<dim3(S_DIM / 128, NBUCKET), 256, sA_dyn>>>();

    conv_kernel<<<dim3(S_DIM / 64, T_DIM / 32), 256>>>(sig, (float*)d_out);
}